// round 1
// baseline (speedup 1.0000x reference)
#include <cuda_runtime.h>
#include <cuda_bf16.h>
#include <math.h>

// Problem constants
#define BB 16
#define SS 512
#define DD 128
#define HH 8
#define DKK 16
#define NCONV 4
#define KSZ 7
#define MROWS (BB*SS)          // 8192
#define LN_EPS 1e-5f

// ---------------- scratch (device globals; no runtime allocation) ----------
__device__ float g_h  [MROWS*DD];    // LN output
__device__ float g_y  [MROWS*DD];    // depthwise / ffn intermediate
__device__ float g_qkv[MROWS*384];   // packed q|k|v per row
__device__ float g_att[MROWS*DD];    // attention output (pre-Wo)
__device__ float g_wqkv[DD*384];     // packed qkv weights [d][w*128 + h*16 + k]

// ---------------- weight repack: Wq/Wk/Wv [H,D,DK] -> [D, 3*128] -----------
__global__ void repack_qkv_k(const float* __restrict__ Wq,
                             const float* __restrict__ Wk,
                             const float* __restrict__ Wv) {
    int idx = blockIdx.x * blockDim.x + threadIdx.x;
    if (idx >= 3*HH*DD*DKK) return;
    int w = idx / (HH*DD*DKK);
    int r = idx % (HH*DD*DKK);
    int h = r / (DD*DKK);
    int r2 = r % (DD*DKK);
    int d = r2 / DKK;
    int k = r2 % DKK;
    const float* W = (w == 0) ? Wq : (w == 1) ? Wk : Wv;
    g_wqkv[d*384 + w*128 + h*DKK + k] = W[h*DD*DKK + d*DKK + k];
}

// ---------------- positional signal add ------------------------------------
__global__ void pos_add_k(const float* __restrict__ x, float* __restrict__ out) {
    int idx = blockIdx.x * blockDim.x + threadIdx.x;
    if (idx >= MROWS*DD) return;
    int d = idx & (DD-1);
    int s = (idx >> 7) & (SS-1);
    const float inc = 9.210340371976184f / 63.0f; // log(10000)/(nt-1)
    float v;
    if (d < 64) v = sinf((float)s * expf(-(float)d * inc));
    else        v = cosf((float)s * expf(-(float)(d-64) * inc));
    out[idx] = x[idx] + v;
}

// ---------------- LayerNorm: warp per row (D=128, float4 per lane) ---------
__global__ void ln_k(const float* __restrict__ in, float* __restrict__ out,
                     const float* __restrict__ gamma, const float* __restrict__ beta) {
    int warp = threadIdx.x >> 5;
    int lane = threadIdx.x & 31;
    int row  = blockIdx.x * 8 + warp;
    if (row >= MROWS) return;
    float4 v = ((const float4*)(in + (size_t)row*DD))[lane];
    float sum = v.x + v.y + v.z + v.w;
    #pragma unroll
    for (int o = 16; o; o >>= 1) sum += __shfl_xor_sync(0xffffffffu, sum, o);
    float mu = sum * (1.0f/128.0f);
    float dx = v.x-mu, dy = v.y-mu, dz = v.z-mu, dw = v.w-mu;
    float sq = dx*dx + dy*dy + dz*dz + dw*dw;
    #pragma unroll
    for (int o = 16; o; o >>= 1) sq += __shfl_xor_sync(0xffffffffu, sq, o);
    float rstd = rsqrtf(sq * (1.0f/128.0f) + LN_EPS);
    float4 gg = ((const float4*)gamma)[lane];
    float4 bb = ((const float4*)beta)[lane];
    float4 r;
    r.x = dx*rstd*gg.x + bb.x;
    r.y = dy*rstd*gg.y + bb.y;
    r.z = dz*rstd*gg.z + bb.z;
    r.w = dw*rstd*gg.w + bb.w;
    ((float4*)(out + (size_t)row*DD))[lane] = r;
}

// ---------------- depthwise conv along S (k=7, pad=3), [B,S,D] layout ------
__global__ void dwconv_k(const float* __restrict__ h, float* __restrict__ y,
                         const float* __restrict__ dw_w, const float* __restrict__ dw_b,
                         int layer) {
    int s = blockIdx.x & (SS-1);
    int b = blockIdx.x >> 9;
    int d = threadIdx.x;
    const float* wp = dw_w + (size_t)layer*DD*KSZ + d*KSZ;
    float acc = dw_b[layer*DD + d];
    size_t base = (size_t)b*SS*DD + d;
    #pragma unroll
    for (int j = 0; j < KSZ; j++) {
        int ss = s - 3 + j;
        if ((unsigned)ss < SS) acc += h[base + (size_t)ss*DD] * wp[j];
    }
    y[((size_t)b*SS + s)*DD + d] = acc;
}

// ---------------- tiled fp32 GEMM: C[M,N] = A[M,128] * B (+bias)(relu)(+res)
// BM=64, BN=128, BK=16, 256 threads, 8x4 micro-tile
// TRANSB: B is [N,128] row-major (use B^T);  else B is [128, ldb] row-major.
// BIAS: 0 none, 1 per-column vector, 2 scalar (bias[0])
template<bool TRANSB, int BIAS, bool RELU, bool RES>
__global__ void gemm_k(const float* __restrict__ A, const float* __restrict__ Bm,
                       const float* __restrict__ bias, const float* __restrict__ res,
                       float* __restrict__ C, int N, int ldb) {
    __shared__ float As[16][64];
    __shared__ float Bs[16][128];
    int m0 = blockIdx.x * 64;
    int n0 = blockIdx.y * 128;
    int tid = threadIdx.x;
    int tx = tid & 31, ty = tid >> 5;
    float acc[8][4];
    #pragma unroll
    for (int i = 0; i < 8; i++)
        #pragma unroll
        for (int j = 0; j < 4; j++) acc[i][j] = 0.0f;

    for (int k0 = 0; k0 < 128; k0 += 16) {
        { // load A tile (transposed into As[k][m])
            int m = tid >> 2;
            int kq = (tid & 3) * 4;
            float4 a = *(const float4*)(A + (size_t)(m0+m)*128 + k0 + kq);
            As[kq+0][m] = a.x; As[kq+1][m] = a.y; As[kq+2][m] = a.z; As[kq+3][m] = a.w;
        }
        if (TRANSB) { // B[n][k], stride 128
            int n = tid >> 1;
            int kq = (tid & 1) * 8;
            float4 b1 = *(const float4*)(Bm + (size_t)(n0+n)*128 + k0 + kq);
            float4 b2 = *(const float4*)(Bm + (size_t)(n0+n)*128 + k0 + kq + 4);
            Bs[kq+0][n] = b1.x; Bs[kq+1][n] = b1.y; Bs[kq+2][n] = b1.z; Bs[kq+3][n] = b1.w;
            Bs[kq+4][n] = b2.x; Bs[kq+5][n] = b2.y; Bs[kq+6][n] = b2.z; Bs[kq+7][n] = b2.w;
        } else {      // B[k][n], stride ldb
            int kk = tid >> 5;
            int n  = (tid & 31) * 4;
            float4 b1 = *(const float4*)(Bm + (size_t)(k0+kk)*ldb + n0 + n);
            Bs[kk][n+0] = b1.x; Bs[kk][n+1] = b1.y; Bs[kk][n+2] = b1.z; Bs[kk][n+3] = b1.w;
            float4 b2 = *(const float4*)(Bm + (size_t)(k0+kk+8)*ldb + n0 + n);
            Bs[kk+8][n+0] = b2.x; Bs[kk+8][n+1] = b2.y; Bs[kk+8][n+2] = b2.z; Bs[kk+8][n+3] = b2.w;
        }
        __syncthreads();
        #pragma unroll
        for (int kk = 0; kk < 16; kk++) {
            float4 a0 = *(const float4*)&As[kk][ty*8];
            float4 a1 = *(const float4*)&As[kk][ty*8+4];
            float4 bv = *(const float4*)&Bs[kk][tx*4];
            float a[8] = {a0.x,a0.y,a0.z,a0.w,a1.x,a1.y,a1.z,a1.w};
            float bb[4] = {bv.x,bv.y,bv.z,bv.w};
            #pragma unroll
            for (int i = 0; i < 8; i++)
                #pragma unroll
                for (int j = 0; j < 4; j++) acc[i][j] += a[i]*bb[j];
        }
        __syncthreads();
    }

    int n = n0 + tx*4;
    float4 bvec = make_float4(0.f,0.f,0.f,0.f);
    if (BIAS == 1) bvec = *(const float4*)(bias + n);
    float bscal = (BIAS == 2) ? bias[0] : 0.0f;
    #pragma unroll
    for (int i = 0; i < 8; i++) {
        int m = m0 + ty*8 + i;
        float4 v = make_float4(acc[i][0], acc[i][1], acc[i][2], acc[i][3]);
        if (BIAS == 1) { v.x += bvec.x; v.y += bvec.y; v.z += bvec.z; v.w += bvec.w; }
        if (BIAS == 2) { v.x += bscal; v.y += bscal; v.z += bscal; v.w += bscal; }
        if (RELU) { v.x = fmaxf(v.x,0.f); v.y = fmaxf(v.y,0.f); v.z = fmaxf(v.z,0.f); v.w = fmaxf(v.w,0.f); }
        if (RES) {
            float4 r = *(const float4*)(res + (size_t)m*N + n);
            v.x += r.x; v.y += r.y; v.z += r.z; v.w += r.w;
        }
        *(float4*)(C + (size_t)m*N + n) = v;
    }
}

// ---------------- attention: one block per (b,h); K/V resident in smem -----
__global__ void attention_k(const float* __restrict__ qkv, const int* __restrict__ mask,
                            float* __restrict__ out) {
    extern __shared__ float sm[];
    float* Ks = sm;                 // [512][17]
    float* Vs = sm + 512*17;        // [512][17]
    float* mb = Vs + 512*17;        // [512]
    int bh = blockIdx.x;
    int b = bh >> 3, h = bh & 7;
    int tid = threadIdx.x;

    for (int idx = tid; idx < SS*DKK; idx += 256) {
        int t = idx >> 4, j = idx & 15;
        const float* row = qkv + (size_t)(b*SS + t)*384;
        Ks[t*17 + j] = row[128 + h*DKK + j];
        Vs[t*17 + j] = row[256 + h*DKK + j];
    }
    for (int t = tid; t < SS; t += 256)
        mb[t] = mask[b*SS + t] ? 0.0f : -1e30f;
    __syncthreads();

    int lane = tid & 31, warp = tid >> 5;
    for (int s = warp; s < SS; s += 8) {
        const float* qrow = qkv + (size_t)(b*SS + s)*384 + h*DKK;
        float q[16];
        #pragma unroll
        for (int j = 0; j < 16; j++) q[j] = qrow[j];

        float sc[16];
        float mx = -3.4e38f;
        #pragma unroll
        for (int i = 0; i < 16; i++) {
            int t = lane + 32*i;
            const float* kr = Ks + t*17;
            float a = 0.f;
            #pragma unroll
            for (int j = 0; j < 16; j++) a += q[j]*kr[j];
            a = a * 0.25f + mb[t];
            sc[i] = a;
            mx = fmaxf(mx, a);
        }
        #pragma unroll
        for (int o = 16; o; o >>= 1) mx = fmaxf(mx, __shfl_xor_sync(0xffffffffu, mx, o));
        float sum = 0.f;
        #pragma unroll
        for (int i = 0; i < 16; i++) { sc[i] = __expf(sc[i]-mx); sum += sc[i]; }
        #pragma unroll
        for (int o = 16; o; o >>= 1) sum += __shfl_xor_sync(0xffffffffu, sum, o);
        float inv = 1.0f / sum;

        float acc[16];
        #pragma unroll
        for (int j = 0; j < 16; j++) acc[j] = 0.f;
        #pragma unroll
        for (int i = 0; i < 16; i++) {
            float p = sc[i] * inv;
            const float* vr = Vs + (lane + 32*i)*17;
            #pragma unroll
            for (int j = 0; j < 16; j++) acc[j] += p * vr[j];
        }
        #pragma unroll
        for (int j = 0; j < 16; j++) {
            float v = acc[j];
            #pragma unroll
            for (int o = 16; o; o >>= 1) v += __shfl_xor_sync(0xffffffffu, v, o);
            if (lane == j) out[(size_t)(b*SS + s)*DD + h*DKK + j] = v;
        }
    }
}

// ---------------- host launcher --------------------------------------------
extern "C" void kernel_launch(void* const* d_in, const int* in_sizes, int n_in,
                              void* d_out, int out_size) {
    const float* x        = (const float*)d_in[0];
    const int*   mask     = (const int*)  d_in[1];
    const float* ln_scale = (const float*)d_in[2];
    const float* ln_bias  = (const float*)d_in[3];
    const float* dw_w     = (const float*)d_in[4];
    const float* dw_b     = (const float*)d_in[5];
    const float* pw_w     = (const float*)d_in[6];
    const float* pw_b     = (const float*)d_in[7];
    const float* Wq       = (const float*)d_in[8];
    const float* Wk       = (const float*)d_in[9];
    const float* Wv       = (const float*)d_in[10];
    const float* Wo       = (const float*)d_in[11];
    const float* att_bias = (const float*)d_in[12];
    const float* f1_w     = (const float*)d_in[13];
    const float* f1_b     = (const float*)d_in[14];
    const float* f2_w     = (const float*)d_in[15];
    const float* f2_b     = (const float*)d_in[16];
    float* out = (float*)d_out;

    float *ph, *py, *pqkv, *patt, *pwqkv;
    cudaGetSymbolAddress((void**)&ph,    g_h);
    cudaGetSymbolAddress((void**)&py,    g_y);
    cudaGetSymbolAddress((void**)&pqkv,  g_qkv);
    cudaGetSymbolAddress((void**)&patt,  g_att);
    cudaGetSymbolAddress((void**)&pwqkv, g_wqkv);

    // repack qkv weights
    repack_qkv_k<<<(3*HH*DD*DKK + 255)/256, 256>>>(Wq, Wk, Wv);
    // out = x + pos_signal
    pos_add_k<<<(MROWS*DD + 255)/256, 256>>>(x, out);

    // conv stack
    for (int i = 0; i < NCONV; i++) {
        ln_k<<<MROWS/8, 256>>>(out, ph, ln_scale + i*DD, ln_bias + i*DD);
        dwconv_k<<<MROWS, DD>>>(ph, py, dw_w, dw_b, i);
        // pointwise: out = relu(y @ pw^T + pw_b) + out
        gemm_k<true, 1, true, true><<<dim3(MROWS/64, 1), 256>>>(
            py, pw_w + (size_t)i*DD*DD, pw_b + i*DD, out, out, 128, 128);
    }

    // attention
    ln_k<<<MROWS/8, 256>>>(out, ph, ln_scale + NCONV*DD, ln_bias + NCONV*DD);
    gemm_k<false, 2, false, false><<<dim3(MROWS/64, 3), 256>>>(
        ph, pwqkv, att_bias, nullptr, pqkv, 384, 384);
    cudaFuncSetAttribute(attention_k, cudaFuncAttributeMaxDynamicSharedMemorySize, 71680);
    attention_k<<<BB*HH, 256, 71680>>>(pqkv, mask, patt);
    gemm_k<false, 2, false, true><<<dim3(MROWS/64, 1), 256>>>(
        patt, Wo, att_bias, out, out, 128, 128);

    // feed-forward
    ln_k<<<MROWS/8, 256>>>(out, ph, ln_scale + (NCONV+1)*DD, ln_bias + (NCONV+1)*DD);
    gemm_k<true, 1, true, false><<<dim3(MROWS/64, 1), 256>>>(
        ph, f1_w, f1_b, nullptr, py, 128, 128);
    gemm_k<true, 1, false, true><<<dim3(MROWS/64, 1), 256>>>(
        py, f2_w, f2_b, out, out, 128, 128);
}

// round 4
// speedup vs baseline: 1.5663x; 1.5663x over previous
#include <cuda_runtime.h>
#include <cuda_bf16.h>
#include <math.h>
#include <string.h>

// Problem constants
#define BB 16
#define SS 512
#define DD 128
#define HH 8
#define DKK 16
#define NCONV 4
#define KSZ 7
#define MROWS (BB*SS)          // 8192
#define LN_EPS 1e-5f

typedef unsigned long long u64;
typedef unsigned int u32;

// ---------------- scratch (device globals) ---------------------------------
__device__ float g_h  [MROWS*DD];     // LN output
__device__ float g_y  [MROWS*DD];     // depthwise / ffn intermediate
__device__ float g_qkv[MROWS*384];    // packed q|k|v per row
__device__ float g_att[MROWS*DD];     // attention output (pre-Wo)
// weights as bf16 hi/lo, packed 2-per-u32 along k. Per unit: N*64 u32 hi, then N*64 u32 lo.
__device__ u32   g_wt [163840];

#define PW_OFF   0        // 4 units of 16384 (hi 8192 | lo 8192)
#define QKV_OFF  65536    // hi 24576 | lo 24576
#define WO_OFF   114688   // hi 8192 | lo 8192
#define F1_OFF   131072
#define F2_OFF   147456

// ---------------- helpers ---------------------------------------------------
__device__ __forceinline__ u64 fma2(u64 a, u64 b, u64 c) {
    u64 d; asm("fma.rn.f32x2 %0, %1, %2, %3;" : "=l"(d) : "l"(a), "l"(b), "l"(c));
    return d;
}
__device__ __forceinline__ u64 pack2(float x, float y) {
    u64 r; asm("mov.b64 %0, {%1, %2};" : "=l"(r) : "f"(x), "f"(y)); return r;
}
__device__ __forceinline__ float2 unpack2(u64 u) {
    float2 v; asm("mov.b64 {%0, %1}, %2;" : "=f"(v.x), "=f"(v.y) : "l"(u)); return v;
}
__device__ __forceinline__ u32 h2u(__nv_bfloat162 h) {
    u32 u; memcpy(&u, &h, 4); return u;
}
// split (x,y) into packed bf16 hi and lo
__device__ __forceinline__ void split2(float x, float y, u32& hi, u32& lo) {
    __nv_bfloat16 hx = __float2bfloat16(x);
    __nv_bfloat16 hy = __float2bfloat16(y);
    float rx = x - __bfloat162float(hx);
    float ry = y - __bfloat162float(hy);
    __nv_bfloat162 h; h.x = hx; h.y = hy;
    __nv_bfloat162 l; l.x = __float2bfloat16(rx); l.y = __float2bfloat16(ry);
    hi = h2u(h); lo = h2u(l);
}

// ---------------- weight prep: split all GEMM weights into bf16 hi/lo ------
__device__ __forceinline__ float wsrc(int idx,
        const float* pw_w, const float* Wq, const float* Wk, const float* Wv,
        const float* Wo, const float* f1_w, const float* f2_w) {
    if (idx < QKV_OFF) return pw_w[idx];               // [l][n][k]
    if (idx < WO_OFF) {                                // qkv: n=w*128+h*16+kk, k=d
        int r = idx - QKV_OFF;
        int n = r >> 7, k = r & 127;
        int w = n >> 7, h = (n >> 4) & 7, kk = n & 15;
        const float* W = (w == 0) ? Wq : (w == 1) ? Wk : Wv;
        return W[(h*DD + k)*DKK + kk];
    }
    if (idx < F1_OFF) {                                // wo^T
        int r = idx - WO_OFF;
        int n = r >> 7, k = r & 127;
        return Wo[k*DD + n];
    }
    if (idx < F2_OFF) return f1_w[idx - F1_OFF];
    return f2_w[idx - F2_OFF];
}

__global__ void prep_weights_k(const float* __restrict__ pw_w,
                               const float* __restrict__ Wq,
                               const float* __restrict__ Wk,
                               const float* __restrict__ Wv,
                               const float* __restrict__ Wo,
                               const float* __restrict__ f1_w,
                               const float* __restrict__ f2_w) {
    int p = blockIdx.x * blockDim.x + threadIdx.x;
    if (p >= 81920) return;
    int e = p * 2;
    float v0 = wsrc(e,   pw_w, Wq, Wk, Wv, Wo, f1_w, f2_w);
    float v1 = wsrc(e+1, pw_w, Wq, Wk, Wv, Wo, f1_w, f2_w);
    u32 hi, lo;
    split2(v0, v1, hi, lo);
    int base, losz, r;
    if (e < QKV_OFF)      { int unit = e >> 14; base = unit*16384; r = e & 16383; losz = 8192; }
    else if (e < WO_OFF)  { base = QKV_OFF; r = e - QKV_OFF; losz = 24576; }
    else if (e < F1_OFF)  { base = WO_OFF;  r = e - WO_OFF;  losz = 8192; }
    else if (e < F2_OFF)  { base = F1_OFF;  r = e - F1_OFF;  losz = 8192; }
    else                  { base = F2_OFF;  r = e - F2_OFF;  losz = 8192; }
    int n = r >> 7, kp = (r >> 1) & 63;
    g_wt[base + n*64 + kp]        = hi;
    g_wt[base + losz + n*64 + kp] = lo;
}

// ---------------- positional signal add ------------------------------------
__global__ void pos_add_k(const float* __restrict__ x, float* __restrict__ out) {
    int idx = blockIdx.x * blockDim.x + threadIdx.x;
    if (idx >= MROWS*DD) return;
    int d = idx & (DD-1);
    int s = (idx >> 7) & (SS-1);
    const float inc = 9.210340371976184f / 63.0f;
    float v;
    if (d < 64) v = sinf((float)s * expf(-(float)d * inc));
    else        v = cosf((float)s * expf(-(float)(d-64) * inc));
    out[idx] = x[idx] + v;
}

// ---------------- LayerNorm: warp per row ----------------------------------
__global__ void ln_k(const float* __restrict__ in, float* __restrict__ out,
                     const float* __restrict__ gamma, const float* __restrict__ beta) {
    int warp = threadIdx.x >> 5;
    int lane = threadIdx.x & 31;
    int row  = blockIdx.x * 8 + warp;
    if (row >= MROWS) return;
    float4 v = ((const float4*)(in + (size_t)row*DD))[lane];
    float sum = v.x + v.y + v.z + v.w;
    #pragma unroll
    for (int o = 16; o; o >>= 1) sum += __shfl_xor_sync(0xffffffffu, sum, o);
    float mu = sum * (1.0f/128.0f);
    float dx = v.x-mu, dy = v.y-mu, dz = v.z-mu, dw = v.w-mu;
    float sq = dx*dx + dy*dy + dz*dz + dw*dw;
    #pragma unroll
    for (int o = 16; o; o >>= 1) sq += __shfl_xor_sync(0xffffffffu, sq, o);
    float rstd = rsqrtf(sq * (1.0f/128.0f) + LN_EPS);
    float4 gg = ((const float4*)gamma)[lane];
    float4 bb = ((const float4*)beta)[lane];
    float4 r;
    r.x = dx*rstd*gg.x + bb.x;
    r.y = dy*rstd*gg.y + bb.y;
    r.z = dz*rstd*gg.z + bb.z;
    r.w = dw*rstd*gg.w + bb.w;
    ((float4*)(out + (size_t)row*DD))[lane] = r;
}

// ---------------- depthwise conv (k=7, pad=3), float4 over d ---------------
__global__ void dwconv_k(const float* __restrict__ h, float* __restrict__ y,
                         const float* __restrict__ dw_w, const float* __restrict__ dw_b,
                         int layer) {
    int tid = threadIdx.x;
    int d4 = tid & 31;
    int si = tid >> 5;
    int row = blockIdx.x * 8 + si;
    int b = row >> 9, s = row & (SS-1);
    int d0 = d4 * 4;
    float w[4][KSZ];
    #pragma unroll
    for (int c = 0; c < 4; c++)
        #pragma unroll
        for (int j = 0; j < KSZ; j++)
            w[c][j] = dw_w[((size_t)layer*DD + d0 + c)*KSZ + j];
    float4 acc;
    acc.x = dw_b[layer*DD + d0 + 0];
    acc.y = dw_b[layer*DD + d0 + 1];
    acc.z = dw_b[layer*DD + d0 + 2];
    acc.w = dw_b[layer*DD + d0 + 3];
    size_t base = (size_t)(b*SS)*DD + d0;
    #pragma unroll
    for (int j = 0; j < KSZ; j++) {
        int ss = s - 3 + j;
        if ((unsigned)ss < SS) {
            float4 hv = *(const float4*)(h + base + (size_t)ss*DD);
            acc.x += hv.x * w[0][j];
            acc.y += hv.y * w[1][j];
            acc.z += hv.z * w[2][j];
            acc.w += hv.w * w[3][j];
        }
    }
    *(float4*)(y + (size_t)row*DD + d0) = acc;
}

// ---------------- bf16x3 tensor-core GEMM ----------------------------------
// C[M,Nld] = A[M,128] * W[N,128]^T (+bias)(relu)(+res), fp32-accurate via
// hi/lo bf16 split: Ahi*Bhi + Alo*Bhi + Ahi*Blo.
// Block: 128 threads = 4 warps; tile 64(M) x 128(N); K=128 resident.
#define H2S 68   // half2-stride (u32 units) per row
#define MMA_BF16(acc, a, b) \
    asm volatile("mma.sync.aligned.m16n8k16.row.col.f32.bf16.bf16.f32 " \
        "{%0,%1,%2,%3}, {%4,%5,%6,%7}, {%8,%9}, {%0,%1,%2,%3};\n" \
        : "+f"(acc[0]), "+f"(acc[1]), "+f"(acc[2]), "+f"(acc[3]) \
        : "r"(a[0]), "r"(a[1]), "r"(a[2]), "r"(a[3]), "r"(b[0]), "r"(b[1]))

template<int BIAS, bool RELU, bool RES>
__global__ __launch_bounds__(128) void gemm_bf16x3(
        const float* __restrict__ A, const u32* __restrict__ Whi,
        const u32* __restrict__ Wlo,
        const float* __restrict__ bias, const float* res,
        float* C, int Nld) {
    extern __shared__ u32 smg[];
    u32* Ah = smg;                    // [64][H2S]
    u32* Al = Ah + 64*H2S;
    u32* Bh = Al + 64*H2S;            // [128][H2S]
    u32* Bl = Bh + 128*H2S;
    int tid = threadIdx.x;
    int m0 = blockIdx.x * 64;
    int n0 = blockIdx.y * 128;

    // A tile: load fp32, split to bf16 hi/lo packed pairs
    #pragma unroll
    for (int i = 0; i < 16; i++) {
        int idx = i*128 + tid;
        int r = idx >> 5, c = (idx & 31) << 2;      // fp32 col
        float4 v = *(const float4*)(A + (size_t)(m0+r)*128 + c);
        u32 h0, l0, h1, l1;
        split2(v.x, v.y, h0, l0);
        split2(v.z, v.w, h1, l1);
        int o = r*H2S + (c >> 1);
        Ah[o] = h0; Ah[o+1] = h1;
        Al[o] = l0; Al[o+1] = l1;
    }
    // B tile: prepacked hi/lo, rows offset by n0 (!)
    #pragma unroll
    for (int i = 0; i < 16; i++) {
        int idx = i*128 + tid;                      // uint4 index, 2048 total
        int r = idx >> 4, c4 = (idx & 15) << 2;
        *(uint4*)(Bh + r*H2S + c4) = *(const uint4*)(Whi + (size_t)(n0+r)*64 + c4);
        *(uint4*)(Bl + r*H2S + c4) = *(const uint4*)(Wlo + (size_t)(n0+r)*64 + c4);
    }
    __syncthreads();

    int warp = tid >> 5, lane = tid & 31;
    int g = lane >> 2, tg = lane & 3;
    float acc[4][4][4];
    #pragma unroll
    for (int mi = 0; mi < 4; mi++)
        #pragma unroll
        for (int ni = 0; ni < 4; ni++)
            #pragma unroll
            for (int c = 0; c < 4; c++) acc[mi][ni][c] = 0.0f;

    #pragma unroll
    for (int kt = 0; kt < 8; kt++) {
        int kb = kt * 8;     // h2 offset of this k16 chunk
        u32 ah[4][4], al[4][4], bh[4][2], bl[4][2];
        #pragma unroll
        for (int mi = 0; mi < 4; mi++) {
            const u32* p = Ah + (mi*16 + g)*H2S + kb + tg;
            ah[mi][0] = p[0]; ah[mi][1] = p[8*H2S]; ah[mi][2] = p[4]; ah[mi][3] = p[8*H2S + 4];
            const u32* q = Al + (mi*16 + g)*H2S + kb + tg;
            al[mi][0] = q[0]; al[mi][1] = q[8*H2S]; al[mi][2] = q[4]; al[mi][3] = q[8*H2S + 4];
        }
        #pragma unroll
        for (int ni = 0; ni < 4; ni++) {
            const u32* p = Bh + (warp*32 + ni*8 + g)*H2S + kb + tg;
            bh[ni][0] = p[0]; bh[ni][1] = p[4];
            const u32* q = Bl + (warp*32 + ni*8 + g)*H2S + kb + tg;
            bl[ni][0] = q[0]; bl[ni][1] = q[4];
        }
        #pragma unroll
        for (int mi = 0; mi < 4; mi++)
            #pragma unroll
            for (int ni = 0; ni < 4; ni++) {
                MMA_BF16(acc[mi][ni], ah[mi], bh[ni]);
                MMA_BF16(acc[mi][ni], al[mi], bh[ni]);
                MMA_BF16(acc[mi][ni], ah[mi], bl[ni]);
            }
    }

    float bscal = (BIAS == 2) ? bias[0] : 0.0f;
    #pragma unroll
    for (int ni = 0; ni < 4; ni++) {
        int col = n0 + warp*32 + ni*8 + 2*tg;
        float2 bv = make_float2(bscal, bscal);
        if (BIAS == 1) bv = *(const float2*)(bias + col);
        #pragma unroll
        for (int mi = 0; mi < 4; mi++) {
            int r0 = m0 + mi*16 + g;
            float2 v0 = make_float2(acc[mi][ni][0] + bv.x, acc[mi][ni][1] + bv.y);
            float2 v1 = make_float2(acc[mi][ni][2] + bv.x, acc[mi][ni][3] + bv.y);
            if (RELU) {
                v0.x = fmaxf(v0.x, 0.f); v0.y = fmaxf(v0.y, 0.f);
                v1.x = fmaxf(v1.x, 0.f); v1.y = fmaxf(v1.y, 0.f);
            }
            if (RES) {
                float2 r0v = *(const float2*)(res + (size_t)r0*Nld + col);
                float2 r1v = *(const float2*)(res + (size_t)(r0+8)*Nld + col);
                v0.x += r0v.x; v0.y += r0v.y;
                v1.x += r1v.x; v1.y += r1v.y;
            }
            *(float2*)(C + (size_t)r0*Nld + col) = v0;
            *(float2*)(C + (size_t)(r0+8)*Nld + col) = v1;
        }
    }
}

// ---------------- attention: f32x2 packed, 4 queries share K/V loads -------
#define KVSTRIDE 18
__global__ __launch_bounds__(256) void attention_k(
        const float* __restrict__ qkv, const int* __restrict__ mask,
        float* __restrict__ out) {
    extern __shared__ float sm[];
    float* Ks = sm;                       // [512][18]
    float* Vs = sm + 512*KVSTRIDE;        // [512][18]
    float* mb = sm + 2*512*KVSTRIDE;      // [512]
    int bh = blockIdx.x;
    int b = bh >> 3, h = bh & 7;
    int tid = threadIdx.x;

    for (int idx = tid; idx < SS*4; idx += 256) {
        int t = idx >> 2, j4 = (idx & 3) * 4;
        const float* row = qkv + (size_t)(b*SS + t)*384 + h*DKK;
        float4 kv = *(const float4*)(row + 128 + j4);
        float4 vv = *(const float4*)(row + 256 + j4);
        float* kd = Ks + t*KVSTRIDE + j4;
        float* vd = Vs + t*KVSTRIDE + j4;
        *(float2*)(kd)   = make_float2(kv.x, kv.y);
        *(float2*)(kd+2) = make_float2(kv.z, kv.w);
        *(float2*)(vd)   = make_float2(vv.x, vv.y);
        *(float2*)(vd+2) = make_float2(vv.z, vv.w);
    }
    for (int t = tid; t < SS; t += 256)
        mb[t] = mask[b*SS + t] ? 0.0f : -1e30f;
    __syncthreads();

    int lane = tid & 31, warp = tid >> 5;
    int qbase = blockIdx.y * 128;

    for (int gq = 0; gq < 4; gq++) {
        int s0 = qbase + warp*16 + gq*4;
        u64 q2[4][8];
        #pragma unroll
        for (int qi = 0; qi < 4; qi++) {
            const float* qp = qkv + (size_t)(b*SS + s0 + qi)*384 + h*DKK;
            #pragma unroll
            for (int j2 = 0; j2 < 8; j2++) {
                float2 t2 = *(const float2*)(qp + 2*j2);
                q2[qi][j2] = pack2(t2.x, t2.y);
            }
        }
        float sc[4][16];
        #pragma unroll
        for (int i = 0; i < 16; i++) {
            int t = i*32 + lane;
            const float* kr = Ks + t*KVSTRIDE;
            float mbv = mb[t];
            u64 a0 = 0, a1 = 0, a2 = 0, a3 = 0;
            #pragma unroll
            for (int j2 = 0; j2 < 8; j2++) {
                u64 k2 = *(const u64*)(kr + 2*j2);
                a0 = fma2(q2[0][j2], k2, a0);
                a1 = fma2(q2[1][j2], k2, a1);
                a2 = fma2(q2[2][j2], k2, a2);
                a3 = fma2(q2[3][j2], k2, a3);
            }
            float2 f;
            f = unpack2(a0); sc[0][i] = (f.x+f.y)*0.25f + mbv;
            f = unpack2(a1); sc[1][i] = (f.x+f.y)*0.25f + mbv;
            f = unpack2(a2); sc[2][i] = (f.x+f.y)*0.25f + mbv;
            f = unpack2(a3); sc[3][i] = (f.x+f.y)*0.25f + mbv;
        }
        #pragma unroll
        for (int qi = 0; qi < 4; qi++) {
            float mx = -3.4e38f;
            #pragma unroll
            for (int i = 0; i < 16; i++) mx = fmaxf(mx, sc[qi][i]);
            #pragma unroll
            for (int o = 16; o; o >>= 1) mx = fmaxf(mx, __shfl_xor_sync(0xffffffffu, mx, o));
            float sum = 0.f;
            #pragma unroll
            for (int i = 0; i < 16; i++) { sc[qi][i] = __expf(sc[qi][i] - mx); sum += sc[qi][i]; }
            #pragma unroll
            for (int o = 16; o; o >>= 1) sum += __shfl_xor_sync(0xffffffffu, sum, o);
            float inv = 1.0f / sum;
            #pragma unroll
            for (int i = 0; i < 16; i++) sc[qi][i] *= inv;
        }
        u64 av[4][8];
        #pragma unroll
        for (int qi = 0; qi < 4; qi++)
            #pragma unroll
            for (int j2 = 0; j2 < 8; j2++) av[qi][j2] = 0;
        #pragma unroll
        for (int i = 0; i < 16; i++) {
            int t = i*32 + lane;
            const float* vr = Vs + t*KVSTRIDE;
            u64 p0 = pack2(sc[0][i], sc[0][i]);
            u64 p1 = pack2(sc[1][i], sc[1][i]);
            u64 p2 = pack2(sc[2][i], sc[2][i]);
            u64 p3 = pack2(sc[3][i], sc[3][i]);
            #pragma unroll
            for (int j2 = 0; j2 < 8; j2++) {
                u64 v2 = *(const u64*)(vr + 2*j2);
                av[0][j2] = fma2(p0, v2, av[0][j2]);
                av[1][j2] = fma2(p1, v2, av[1][j2]);
                av[2][j2] = fma2(p2, v2, av[2][j2]);
                av[3][j2] = fma2(p3, v2, av[3][j2]);
            }
        }
        #pragma unroll
        for (int qi = 0; qi < 4; qi++)
            #pragma unroll
            for (int j2 = 0; j2 < 8; j2++) {
                u64 v = av[qi][j2];
                #pragma unroll
                for (int o = 16; o; o >>= 1) {
                    u64 w = __shfl_xor_sync(0xffffffffu, v, o);
                    float2 x = unpack2(v), y = unpack2(w);
                    v = pack2(x.x + y.x, x.y + y.y);
                }
                av[qi][j2] = v;
            }
        #pragma unroll
        for (int qi = 0; qi < 4; qi++)
            #pragma unroll
            for (int j2 = 0; j2 < 8; j2++)
                if (lane == qi*8 + j2)
                    *(float2*)(out + (size_t)(b*SS + s0 + qi)*DD + h*DKK + 2*j2) = unpack2(av[qi][j2]);
    }
}

// ---------------- host launcher --------------------------------------------
extern "C" void kernel_launch(void* const* d_in, const int* in_sizes, int n_in,
                              void* d_out, int out_size) {
    const float* x        = (const float*)d_in[0];
    const int*   mask     = (const int*)  d_in[1];
    const float* ln_scale = (const float*)d_in[2];
    const float* ln_bias  = (const float*)d_in[3];
    const float* dw_w     = (const float*)d_in[4];
    const float* dw_b     = (const float*)d_in[5];
    const float* pw_w     = (const float*)d_in[6];
    const float* pw_b     = (const float*)d_in[7];
    const float* Wq       = (const float*)d_in[8];
    const float* Wk       = (const float*)d_in[9];
    const float* Wv       = (const float*)d_in[10];
    const float* Wo       = (const float*)d_in[11];
    const float* att_bias = (const float*)d_in[12];
    const float* f1_w     = (const float*)d_in[13];
    const float* f1_b     = (const float*)d_in[14];
    const float* f2_w     = (const float*)d_in[15];
    const float* f2_b     = (const float*)d_in[16];
    float* out = (float*)d_out;

    float *ph, *py, *pqkv, *patt;
    u32 *pwt;
    cudaGetSymbolAddress((void**)&ph,   g_h);
    cudaGetSymbolAddress((void**)&py,   g_y);
    cudaGetSymbolAddress((void**)&pqkv, g_qkv);
    cudaGetSymbolAddress((void**)&patt, g_att);
    cudaGetSymbolAddress((void**)&pwt,  g_wt);

    const int GSMEM = (64*H2S*2 + 128*H2S*2) * 4;       // 104448
    cudaFuncSetAttribute(gemm_bf16x3<1,true,true>,   cudaFuncAttributeMaxDynamicSharedMemorySize, GSMEM);
    cudaFuncSetAttribute(gemm_bf16x3<2,false,false>, cudaFuncAttributeMaxDynamicSharedMemorySize, GSMEM);
    cudaFuncSetAttribute(gemm_bf16x3<2,false,true>,  cudaFuncAttributeMaxDynamicSharedMemorySize, GSMEM);
    cudaFuncSetAttribute(gemm_bf16x3<1,true,false>,  cudaFuncAttributeMaxDynamicSharedMemorySize, GSMEM);
    cudaFuncSetAttribute(gemm_bf16x3<1,false,true>,  cudaFuncAttributeMaxDynamicSharedMemorySize, GSMEM);
    const int ASMEM = (2*512*KVSTRIDE + 512) * 4;       // 75776
    cudaFuncSetAttribute(attention_k, cudaFuncAttributeMaxDynamicSharedMemorySize, ASMEM);

    prep_weights_k<<<320, 256>>>(pw_w, Wq, Wk, Wv, Wo, f1_w, f2_w);
    pos_add_k<<<(MROWS*DD + 255)/256, 256>>>(x, out);

    // conv stack
    for (int i = 0; i < NCONV; i++) {
        ln_k<<<MROWS/8, 256>>>(out, ph, ln_scale + i*DD, ln_bias + i*DD);
        dwconv_k<<<MROWS/8, 256>>>(ph, py, dw_w, dw_b, i);
        const u32* whi = pwt + PW_OFF + (size_t)i*16384;
        gemm_bf16x3<1,true,true><<<dim3(128,1), 128, GSMEM>>>(
            py, whi, whi + 8192, pw_b + i*DD, out, out, 128);
    }

    // attention
    ln_k<<<MROWS/8, 256>>>(out, ph, ln_scale + NCONV*DD, ln_bias + NCONV*DD);
    gemm_bf16x3<2,false,false><<<dim3(128,3), 128, GSMEM>>>(
        ph, pwt + QKV_OFF, pwt + QKV_OFF + 24576, att_bias, nullptr, pqkv, 384);
    attention_k<<<dim3(BB*HH, 4), 256, ASMEM>>>(pqkv, mask, patt);
    gemm_bf16x3<2,false,true><<<dim3(128,1), 128, GSMEM>>>(
        patt, pwt + WO_OFF, pwt + WO_OFF + 8192, att_bias, out, out, 128);

    // feed-forward
    ln_k<<<MROWS/8, 256>>>(out, ph, ln_scale + (NCONV+1)*DD, ln_bias + (NCONV+1)*DD);
    gemm_bf16x3<1,true,false><<<dim3(128,1), 128, GSMEM>>>(
        ph, pwt + F1_OFF, pwt + F1_OFF + 8192, f1_b, nullptr, py, 128);
    gemm_bf16x3<1,false,true><<<dim3(128,1), 128, GSMEM>>>(
        py, pwt + F2_OFF, pwt + F2_OFF + 8192, f2_b, out, out, 128);
}

// round 5
// speedup vs baseline: 1.9804x; 1.2643x over previous
#include <cuda_runtime.h>
#include <cuda_bf16.h>
#include <math.h>
#include <string.h>

// Problem constants
#define BB 16
#define SS 512
#define DD 128
#define HH 8
#define DKK 16
#define NCONV 4
#define KSZ 7
#define MROWS (BB*SS)          // 8192
#define LN_EPS 1e-5f

typedef unsigned long long u64;
typedef unsigned int u32;

// ---------------- scratch (device globals) ---------------------------------
__device__ float g_x1 [MROWS*DD];     // ping-pong partner of d_out
__device__ float g_qkv[MROWS*384];    // packed q|k|v per row
__device__ float g_att[MROWS*DD];     // attention output (pre-Wo)
// weights as bf16 hi/lo, packed 2-per-u32 along k. Per unit: N*64 u32 hi, then N*64 u32 lo.
__device__ u32   g_wt [163840];

#define PW_OFF   0        // 4 units of 16384 (hi 8192 | lo 8192)
#define QKV_OFF  65536    // hi 24576 | lo 24576
#define WO_OFF   114688   // hi 8192 | lo 8192
#define F1_OFF   131072
#define F2_OFF   147456

// ---------------- helpers ---------------------------------------------------
__device__ __forceinline__ u64 fma2(u64 a, u64 b, u64 c) {
    u64 d; asm("fma.rn.f32x2 %0, %1, %2, %3;" : "=l"(d) : "l"(a), "l"(b), "l"(c));
    return d;
}
__device__ __forceinline__ u64 pack2(float x, float y) {
    u64 r; asm("mov.b64 %0, {%1, %2};" : "=l"(r) : "f"(x), "f"(y)); return r;
}
__device__ __forceinline__ float2 unpack2(u64 u) {
    float2 v; asm("mov.b64 {%0, %1}, %2;" : "=f"(v.x), "=f"(v.y) : "l"(u)); return v;
}
__device__ __forceinline__ u32 h2u(__nv_bfloat162 h) {
    u32 u; memcpy(&u, &h, 4); return u;
}
__device__ __forceinline__ void split2(float x, float y, u32& hi, u32& lo) {
    __nv_bfloat16 hx = __float2bfloat16(x);
    __nv_bfloat16 hy = __float2bfloat16(y);
    float rx = x - __bfloat162float(hx);
    float ry = y - __bfloat162float(hy);
    __nv_bfloat162 h; h.x = hx; h.y = hy;
    __nv_bfloat162 l; l.x = __float2bfloat16(rx); l.y = __float2bfloat16(ry);
    hi = h2u(h); lo = h2u(l);
}

// ---------------- weight prep (verbatim from R4, verified) -----------------
__device__ __forceinline__ float wsrc(int idx,
        const float* pw_w, const float* Wq, const float* Wk, const float* Wv,
        const float* Wo, const float* f1_w, const float* f2_w) {
    if (idx < QKV_OFF) return pw_w[idx];
    if (idx < WO_OFF) {
        int r = idx - QKV_OFF;
        int n = r >> 7, k = r & 127;
        int w = n >> 7, h = (n >> 4) & 7, kk = n & 15;
        const float* W = (w == 0) ? Wq : (w == 1) ? Wk : Wv;
        return W[(h*DD + k)*DKK + kk];
    }
    if (idx < F1_OFF) {
        int r = idx - WO_OFF;
        int n = r >> 7, k = r & 127;
        return Wo[k*DD + n];
    }
    if (idx < F2_OFF) return f1_w[idx - F1_OFF];
    return f2_w[idx - F2_OFF];
}

__global__ void prep_weights_k(const float* __restrict__ pw_w,
                               const float* __restrict__ Wq,
                               const float* __restrict__ Wk,
                               const float* __restrict__ Wv,
                               const float* __restrict__ Wo,
                               const float* __restrict__ f1_w,
                               const float* __restrict__ f2_w) {
    int p = blockIdx.x * blockDim.x + threadIdx.x;
    if (p >= 81920) return;
    int e = p * 2;
    float v0 = wsrc(e,   pw_w, Wq, Wk, Wv, Wo, f1_w, f2_w);
    float v1 = wsrc(e+1, pw_w, Wq, Wk, Wv, Wo, f1_w, f2_w);
    u32 hi, lo;
    split2(v0, v1, hi, lo);
    int base, losz, r;
    if (e < QKV_OFF)      { int unit = e >> 14; base = unit*16384; r = e & 16383; losz = 8192; }
    else if (e < WO_OFF)  { base = QKV_OFF; r = e - QKV_OFF; losz = 24576; }
    else if (e < F1_OFF)  { base = WO_OFF;  r = e - WO_OFF;  losz = 8192; }
    else if (e < F2_OFF)  { base = F1_OFF;  r = e - F1_OFF;  losz = 8192; }
    else                  { base = F2_OFF;  r = e - F2_OFF;  losz = 8192; }
    int n = r >> 7, kp = (r >> 1) & 63;
    g_wt[base + n*64 + kp]        = hi;
    g_wt[base + losz + n*64 + kp] = lo;
}

// ---------------- positional signal add ------------------------------------
__global__ void pos_add_k(const float* __restrict__ x, float* __restrict__ out) {
    int idx = blockIdx.x * blockDim.x + threadIdx.x;
    if (idx >= MROWS*DD) return;
    int d = idx & (DD-1);
    int s = (idx >> 7) & (SS-1);
    const float inc = 9.210340371976184f / 63.0f;
    float v;
    if (d < 64) v = sinf((float)s * expf(-(float)d * inc));
    else        v = cosf((float)s * expf(-(float)(d-64) * inc));
    out[idx] = x[idx] + v;
}

// ================= shared GEMM machinery (256 threads, 8 warps) ============
#define H2S 68
#define MMA_BF16(acc, a, b) \
    asm volatile("mma.sync.aligned.m16n8k16.row.col.f32.bf16.bf16.f32 " \
        "{%0,%1,%2,%3}, {%4,%5,%6,%7}, {%8,%9}, {%0,%1,%2,%3};\n" \
        : "+f"(acc[0]), "+f"(acc[1]), "+f"(acc[2]), "+f"(acc[3]) \
        : "r"(a[0]), "r"(a[1]), "r"(a[2]), "r"(a[3]), "r"(b[0]), "r"(b[1]))

// load a [128][64]-u32 prepacked weight matrix pair into smem (8 iters)
__device__ __forceinline__ void load_B(u32* Bh, u32* Bl,
        const u32* __restrict__ Whi, const u32* __restrict__ Wlo, int tid) {
    #pragma unroll
    for (int i = 0; i < 8; i++) {
        int idx = i*256 + tid;
        int r = idx >> 4, c4 = (idx & 15) << 2;
        *(uint4*)(Bh + r*H2S + c4) = *(const uint4*)(Whi + (size_t)r*64 + c4);
        *(uint4*)(Bl + r*H2S + c4) = *(const uint4*)(Wlo + (size_t)r*64 + c4);
    }
}

// per-warp 32x128x... mma main loop: acc[2][4][4]
__device__ __forceinline__ void mma_main(float acc[2][4][4],
        const u32* Ah, const u32* Al, const u32* Bh, const u32* Bl,
        int warpM, int warpN, int g, int tg) {
    #pragma unroll
    for (int kt = 0; kt < 8; kt++) {
        int kb = kt * 8;
        u32 ah[2][4], al[2][4], bh[4][2], bl[4][2];
        #pragma unroll
        for (int mi = 0; mi < 2; mi++) {
            const u32* p = Ah + (warpM*32 + mi*16 + g)*H2S + kb + tg;
            ah[mi][0] = p[0]; ah[mi][1] = p[8*H2S]; ah[mi][2] = p[4]; ah[mi][3] = p[8*H2S + 4];
            const u32* q = Al + (warpM*32 + mi*16 + g)*H2S + kb + tg;
            al[mi][0] = q[0]; al[mi][1] = q[8*H2S]; al[mi][2] = q[4]; al[mi][3] = q[8*H2S + 4];
        }
        #pragma unroll
        for (int ni = 0; ni < 4; ni++) {
            const u32* p = Bh + (warpN*32 + ni*8 + g)*H2S + kb + tg;
            bh[ni][0] = p[0]; bh[ni][1] = p[4];
            const u32* q = Bl + (warpN*32 + ni*8 + g)*H2S + kb + tg;
            bl[ni][0] = q[0]; bl[ni][1] = q[4];
        }
        #pragma unroll
        for (int mi = 0; mi < 2; mi++)
            #pragma unroll
            for (int ni = 0; ni < 4; ni++) {
                MMA_BF16(acc[mi][ni], ah[mi], bh[ni]);
                MMA_BF16(acc[mi][ni], al[mi], bh[ni]);
                MMA_BF16(acc[mi][ni], ah[mi], bl[ni]);
            }
    }
}

// warp-per-row LN of 64 tile rows -> Ah/Al (8 rows per warp)
__device__ __forceinline__ void ln_to_A(u32* Ah, u32* Al,
        const float* __restrict__ X, int m0,
        const float* __restrict__ gamma, const float* __restrict__ beta,
        int warp, int lane) {
    float4 g4 = ((const float4*)gamma)[lane];
    float4 b4 = ((const float4*)beta)[lane];
    #pragma unroll
    for (int i = 0; i < 8; i++) {
        int r = warp*8 + i;
        float4 v = ((const float4*)(X + (size_t)(m0+r)*DD))[lane];
        float sum = v.x + v.y + v.z + v.w;
        #pragma unroll
        for (int o = 16; o; o >>= 1) sum += __shfl_xor_sync(0xffffffffu, sum, o);
        float mu = sum * (1.0f/128.0f);
        float dx = v.x-mu, dy = v.y-mu, dz = v.z-mu, dw = v.w-mu;
        float sq = dx*dx + dy*dy + dz*dz + dw*dw;
        #pragma unroll
        for (int o = 16; o; o >>= 1) sq += __shfl_xor_sync(0xffffffffu, sq, o);
        float rstd = rsqrtf(sq * (1.0f/128.0f) + LN_EPS);
        float nx = dx*rstd*g4.x + b4.x;
        float ny = dy*rstd*g4.y + b4.y;
        float nz = dz*rstd*g4.z + b4.z;
        float nw = dw*rstd*g4.w + b4.w;
        u32 h0, l0, h1, l1;
        split2(nx, ny, h0, l0);
        split2(nz, nw, h1, l1);
        int o2 = r*H2S + lane*2;
        Ah[o2] = h0; Ah[o2+1] = h1;
        Al[o2] = l0; Al[o2+1] = l1;
    }
}

// ---------------- fused conv layer: LN + dwconv + pointwise GEMM -----------
// grid 128, block 256. In -> Out ping-pong. Residual = In.
#define LNS 132
__global__ __launch_bounds__(256) void conv_fused_k(
        const float* __restrict__ In, float* __restrict__ Out,
        const u32* __restrict__ Whi, const u32* __restrict__ Wlo,
        const float* __restrict__ gamma, const float* __restrict__ beta,
        const float* __restrict__ dw_w, const float* __restrict__ dw_b,
        const float* __restrict__ pw_b) {
    extern __shared__ u32 smg[];
    float* LNb = (float*)smg;            // [70][132]
    u32* Ah = smg + 70*LNS;              // [64][68]
    u32* Al = Ah + 64*H2S;
    u32* Bh = Al + 64*H2S;               // [128][68]
    u32* Bl = Bh + 128*H2S;

    int tid = threadIdx.x;
    int warp = tid >> 5, lane = tid & 31;
    int m0 = blockIdx.x * 64;
    int b = m0 >> 9, s0 = m0 & (SS-1);

    // B tile (pointwise weights)
    load_B(Bh, Bl, Whi, Wlo, tid);

    // LN of rows s0-3 .. s0+66 (clamped) into LNb
    float4 g4 = ((const float4*)gamma)[lane];
    float4 be4 = ((const float4*)beta)[lane];
    #pragma unroll
    for (int it = 0; it < 9; it++) {
        int li = warp + it*8;
        if (li >= 70) break;
        int st = s0 - 3 + li;
        if ((unsigned)st < SS) {
            float4 v = ((const float4*)(In + (size_t)(b*SS+st)*DD))[lane];
            float sum = v.x + v.y + v.z + v.w;
            #pragma unroll
            for (int o = 16; o; o >>= 1) sum += __shfl_xor_sync(0xffffffffu, sum, o);
            float mu = sum * (1.0f/128.0f);
            float dx = v.x-mu, dy = v.y-mu, dz = v.z-mu, dw = v.w-mu;
            float sq = dx*dx + dy*dy + dz*dz + dw*dw;
            #pragma unroll
            for (int o = 16; o; o >>= 1) sq += __shfl_xor_sync(0xffffffffu, sq, o);
            float rstd = rsqrtf(sq * (1.0f/128.0f) + LN_EPS);
            float4 r;
            r.x = dx*rstd*g4.x + be4.x;
            r.y = dy*rstd*g4.y + be4.y;
            r.z = dz*rstd*g4.z + be4.z;
            r.w = dw*rstd*g4.w + be4.w;
            *(float4*)(LNb + li*LNS + lane*4) = r;
        }
    }
    __syncthreads();

    // depthwise conv -> A tile (bf16 hi/lo). Thread owns cols c,c+1 for 16 rows.
    {
        int p = tid & 63, rq = tid >> 6;
        int c = 2*p;
        float w0[KSZ], w1[KSZ];
        #pragma unroll
        for (int j = 0; j < KSZ; j++) {
            w0[j] = dw_w[c*KSZ + j];
            w1[j] = dw_w[(c+1)*KSZ + j];
        }
        float bb0 = dw_b[c], bb1 = dw_b[c+1];
        #pragma unroll
        for (int i = 0; i < 16; i++) {
            int r = i*4 + rq;
            float a0 = bb0, a1 = bb1;
            #pragma unroll
            for (int j = 0; j < KSZ; j++) {
                int st = s0 + r - 3 + j;
                if ((unsigned)st < SS) {
                    float2 hv = *(const float2*)(LNb + (r+j)*LNS + c);
                    a0 += hv.x * w0[j];
                    a1 += hv.y * w1[j];
                }
            }
            u32 hi, lo;
            split2(a0, a1, hi, lo);
            Ah[r*H2S + p] = hi;
            Al[r*H2S + p] = lo;
        }
    }
    __syncthreads();

    int warpM = warp >> 2, warpN = warp & 3;
    int g = lane >> 2, tg = lane & 3;
    float acc[2][4][4];
    #pragma unroll
    for (int mi = 0; mi < 2; mi++)
        #pragma unroll
        for (int ni = 0; ni < 4; ni++)
            #pragma unroll
            for (int c = 0; c < 4; c++) acc[mi][ni][c] = 0.0f;

    mma_main(acc, Ah, Al, Bh, Bl, warpM, warpN, g, tg);

    // epilogue: +pw_b, relu, +In (residual), write Out
    #pragma unroll
    for (int ni = 0; ni < 4; ni++) {
        int col = warpN*32 + ni*8 + 2*tg;
        float2 bv = *(const float2*)(pw_b + col);
        #pragma unroll
        for (int mi = 0; mi < 2; mi++) {
            int r0 = m0 + warpM*32 + mi*16 + g;
            float2 v0 = make_float2(fmaxf(acc[mi][ni][0] + bv.x, 0.f),
                                    fmaxf(acc[mi][ni][1] + bv.y, 0.f));
            float2 v1 = make_float2(fmaxf(acc[mi][ni][2] + bv.x, 0.f),
                                    fmaxf(acc[mi][ni][3] + bv.y, 0.f));
            float2 r0v = *(const float2*)(In + (size_t)r0*DD + col);
            float2 r1v = *(const float2*)(In + (size_t)(r0+8)*DD + col);
            v0.x += r0v.x; v0.y += r0v.y;
            v1.x += r1v.x; v1.y += r1v.y;
            *(float2*)(Out + (size_t)r0*DD + col) = v0;
            *(float2*)(Out + (size_t)(r0+8)*DD + col) = v1;
        }
    }
}

// ---------------- fused LN + QKV GEMM (N=384 via grid.y=3) -----------------
__global__ __launch_bounds__(256) void qkv_fused_k(
        const float* __restrict__ In,
        const float* __restrict__ gamma, const float* __restrict__ beta,
        const float* __restrict__ att_bias, float* __restrict__ Outqkv) {
    extern __shared__ u32 smg[];
    u32* Ah = smg;
    u32* Al = Ah + 64*H2S;
    u32* Bh = Al + 64*H2S;
    u32* Bl = Bh + 128*H2S;
    int tid = threadIdx.x;
    int warp = tid >> 5, lane = tid & 31;
    int m0 = blockIdx.x * 64;
    int n0 = blockIdx.y * 128;

    load_B(Bh, Bl, g_wt + QKV_OFF + (size_t)(blockIdx.y)*128*64,
                   g_wt + QKV_OFF + 24576 + (size_t)(blockIdx.y)*128*64, tid);
    ln_to_A(Ah, Al, In, m0, gamma, beta, warp, lane);
    __syncthreads();

    int warpM = warp >> 2, warpN = warp & 3;
    int g = lane >> 2, tg = lane & 3;
    float acc[2][4][4];
    #pragma unroll
    for (int mi = 0; mi < 2; mi++)
        #pragma unroll
        for (int ni = 0; ni < 4; ni++)
            #pragma unroll
            for (int c = 0; c < 4; c++) acc[mi][ni][c] = 0.0f;

    mma_main(acc, Ah, Al, Bh, Bl, warpM, warpN, g, tg);

    float b0 = att_bias[0];
    #pragma unroll
    for (int ni = 0; ni < 4; ni++) {
        int col = n0 + warpN*32 + ni*8 + 2*tg;
        #pragma unroll
        for (int mi = 0; mi < 2; mi++) {
            int r0 = m0 + warpM*32 + mi*16 + g;
            float2 v0 = make_float2(acc[mi][ni][0] + b0, acc[mi][ni][1] + b0);
            float2 v1 = make_float2(acc[mi][ni][2] + b0, acc[mi][ni][3] + b0);
            *(float2*)(Outqkv + (size_t)r0*384 + col) = v0;
            *(float2*)(Outqkv + (size_t)(r0+8)*384 + col) = v1;
        }
    }
}

// ---------------- Wo GEMM (+scalar bias, +res) -----------------------------
__global__ __launch_bounds__(256) void wo_gemm_k(
        const float* __restrict__ A, const float* __restrict__ att_bias,
        const float* __restrict__ res, float* __restrict__ Out) {
    extern __shared__ u32 smg[];
    u32* Ah = smg;
    u32* Al = Ah + 64*H2S;
    u32* Bh = Al + 64*H2S;
    u32* Bl = Bh + 128*H2S;
    int tid = threadIdx.x;
    int warp = tid >> 5, lane = tid & 31;
    int m0 = blockIdx.x * 64;

    load_B(Bh, Bl, g_wt + WO_OFF, g_wt + WO_OFF + 8192, tid);
    // A: fp32 split on load (8 rows per warp)
    #pragma unroll
    for (int i = 0; i < 8; i++) {
        int r = warp*8 + i;
        float4 v = ((const float4*)(A + (size_t)(m0+r)*DD))[lane];
        u32 h0, l0, h1, l1;
        split2(v.x, v.y, h0, l0);
        split2(v.z, v.w, h1, l1);
        int o2 = r*H2S + lane*2;
        Ah[o2] = h0; Ah[o2+1] = h1;
        Al[o2] = l0; Al[o2+1] = l1;
    }
    __syncthreads();

    int warpM = warp >> 2, warpN = warp & 3;
    int g = lane >> 2, tg = lane & 3;
    float acc[2][4][4];
    #pragma unroll
    for (int mi = 0; mi < 2; mi++)
        #pragma unroll
        for (int ni = 0; ni < 4; ni++)
            #pragma unroll
            for (int c = 0; c < 4; c++) acc[mi][ni][c] = 0.0f;

    mma_main(acc, Ah, Al, Bh, Bl, warpM, warpN, g, tg);

    float b0 = att_bias[0];
    #pragma unroll
    for (int ni = 0; ni < 4; ni++) {
        int col = warpN*32 + ni*8 + 2*tg;
        #pragma unroll
        for (int mi = 0; mi < 2; mi++) {
            int r0 = m0 + warpM*32 + mi*16 + g;
            float2 r0v = *(const float2*)(res + (size_t)r0*DD + col);
            float2 r1v = *(const float2*)(res + (size_t)(r0+8)*DD + col);
            float2 v0 = make_float2(acc[mi][ni][0] + b0 + r0v.x, acc[mi][ni][1] + b0 + r0v.y);
            float2 v1 = make_float2(acc[mi][ni][2] + b0 + r1v.x, acc[mi][ni][3] + b0 + r1v.y);
            *(float2*)(Out + (size_t)r0*DD + col) = v0;
            *(float2*)(Out + (size_t)(r0+8)*DD + col) = v1;
        }
    }
}

// ---------------- fused FFN: LN + f1 + relu + f2 + residual ----------------
__global__ __launch_bounds__(256) void ffn_fused_k(
        const float* __restrict__ In,
        const float* __restrict__ gamma, const float* __restrict__ beta,
        const float* __restrict__ f1_b, const float* __restrict__ f2_b,
        float* __restrict__ Out) {
    extern __shared__ u32 smg[];
    u32* Ah  = smg;
    u32* Al  = Ah + 64*H2S;
    u32* Bh1 = Al + 64*H2S;
    u32* Bl1 = Bh1 + 128*H2S;
    u32* Bh2 = Bl1 + 128*H2S;
    u32* Bl2 = Bh2 + 128*H2S;
    int tid = threadIdx.x;
    int warp = tid >> 5, lane = tid & 31;
    int m0 = blockIdx.x * 64;

    load_B(Bh1, Bl1, g_wt + F1_OFF, g_wt + F1_OFF + 8192, tid);
    load_B(Bh2, Bl2, g_wt + F2_OFF, g_wt + F2_OFF + 8192, tid);
    ln_to_A(Ah, Al, In, m0, gamma, beta, warp, lane);
    __syncthreads();

    int warpM = warp >> 2, warpN = warp & 3;
    int g = lane >> 2, tg = lane & 3;
    float acc[2][4][4];
    #pragma unroll
    for (int mi = 0; mi < 2; mi++)
        #pragma unroll
        for (int ni = 0; ni < 4; ni++)
            #pragma unroll
            for (int c = 0; c < 4; c++) acc[mi][ni][c] = 0.0f;

    mma_main(acc, Ah, Al, Bh1, Bl1, warpM, warpN, g, tg);
    __syncthreads();   // all warps done reading Ah/Al

    // relu(acc + f1_b) -> re-split into Ah/Al
    #pragma unroll
    for (int ni = 0; ni < 4; ni++) {
        int col = warpN*32 + ni*8 + 2*tg;
        float2 bv = *(const float2*)(f1_b + col);
        #pragma unroll
        for (int mi = 0; mi < 2; mi++) {
            int r = warpM*32 + mi*16 + g;
            float x0 = fmaxf(acc[mi][ni][0] + bv.x, 0.f);
            float y0 = fmaxf(acc[mi][ni][1] + bv.y, 0.f);
            float x1 = fmaxf(acc[mi][ni][2] + bv.x, 0.f);
            float y1 = fmaxf(acc[mi][ni][3] + bv.y, 0.f);
            u32 hi, lo;
            split2(x0, y0, hi, lo);
            Ah[r*H2S + (col>>1)] = hi; Al[r*H2S + (col>>1)] = lo;
            split2(x1, y1, hi, lo);
            Ah[(r+8)*H2S + (col>>1)] = hi; Al[(r+8)*H2S + (col>>1)] = lo;
        }
    }
    __syncthreads();

    #pragma unroll
    for (int mi = 0; mi < 2; mi++)
        #pragma unroll
        for (int ni = 0; ni < 4; ni++)
            #pragma unroll
            for (int c = 0; c < 4; c++) acc[mi][ni][c] = 0.0f;

    mma_main(acc, Ah, Al, Bh2, Bl2, warpM, warpN, g, tg);

    #pragma unroll
    for (int ni = 0; ni < 4; ni++) {
        int col = warpN*32 + ni*8 + 2*tg;
        float2 bv = *(const float2*)(f2_b + col);
        #pragma unroll
        for (int mi = 0; mi < 2; mi++) {
            int r0 = m0 + warpM*32 + mi*16 + g;
            float2 r0v = *(const float2*)(In + (size_t)r0*DD + col);
            float2 r1v = *(const float2*)(In + (size_t)(r0+8)*DD + col);
            float2 v0 = make_float2(acc[mi][ni][0] + bv.x + r0v.x, acc[mi][ni][1] + bv.y + r0v.y);
            float2 v1 = make_float2(acc[mi][ni][2] + bv.x + r1v.x, acc[mi][ni][3] + bv.y + r1v.y);
            *(float2*)(Out + (size_t)r0*DD + col) = v0;
            *(float2*)(Out + (size_t)(r0+8)*DD + col) = v1;
        }
    }
}

// ---------------- attention (verbatim from R4, verified) -------------------
#define KVSTRIDE 18
__global__ __launch_bounds__(256) void attention_k(
        const float* __restrict__ qkv, const int* __restrict__ mask,
        float* __restrict__ out) {
    extern __shared__ float sm[];
    float* Ks = sm;
    float* Vs = sm + 512*KVSTRIDE;
    float* mb = sm + 2*512*KVSTRIDE;
    int bh = blockIdx.x;
    int b = bh >> 3, h = bh & 7;
    int tid = threadIdx.x;

    for (int idx = tid; idx < SS*4; idx += 256) {
        int t = idx >> 2, j4 = (idx & 3) * 4;
        const float* row = qkv + (size_t)(b*SS + t)*384 + h*DKK;
        float4 kv = *(const float4*)(row + 128 + j4);
        float4 vv = *(const float4*)(row + 256 + j4);
        float* kd = Ks + t*KVSTRIDE + j4;
        float* vd = Vs + t*KVSTRIDE + j4;
        *(float2*)(kd)   = make_float2(kv.x, kv.y);
        *(float2*)(kd+2) = make_float2(kv.z, kv.w);
        *(float2*)(vd)   = make_float2(vv.x, vv.y);
        *(float2*)(vd+2) = make_float2(vv.z, vv.w);
    }
    for (int t = tid; t < SS; t += 256)
        mb[t] = mask[b*SS + t] ? 0.0f : -1e30f;
    __syncthreads();

    int lane = tid & 31, warp = tid >> 5;
    int qbase = blockIdx.y * 128;

    for (int gq = 0; gq < 4; gq++) {
        int s0 = qbase + warp*16 + gq*4;
        u64 q2[4][8];
        #pragma unroll
        for (int qi = 0; qi < 4; qi++) {
            const float* qp = qkv + (size_t)(b*SS + s0 + qi)*384 + h*DKK;
            #pragma unroll
            for (int j2 = 0; j2 < 8; j2++) {
                float2 t2 = *(const float2*)(qp + 2*j2);
                q2[qi][j2] = pack2(t2.x, t2.y);
            }
        }
        float sc[4][16];
        #pragma unroll
        for (int i = 0; i < 16; i++) {
            int t = i*32 + lane;
            const float* kr = Ks + t*KVSTRIDE;
            float mbv = mb[t];
            u64 a0 = 0, a1 = 0, a2 = 0, a3 = 0;
            #pragma unroll
            for (int j2 = 0; j2 < 8; j2++) {
                u64 k2 = *(const u64*)(kr + 2*j2);
                a0 = fma2(q2[0][j2], k2, a0);
                a1 = fma2(q2[1][j2], k2, a1);
                a2 = fma2(q2[2][j2], k2, a2);
                a3 = fma2(q2[3][j2], k2, a3);
            }
            float2 f;
            f = unpack2(a0); sc[0][i] = (f.x+f.y)*0.25f + mbv;
            f = unpack2(a1); sc[1][i] = (f.x+f.y)*0.25f + mbv;
            f = unpack2(a2); sc[2][i] = (f.x+f.y)*0.25f + mbv;
            f = unpack2(a3); sc[3][i] = (f.x+f.y)*0.25f + mbv;
        }
        #pragma unroll
        for (int qi = 0; qi < 4; qi++) {
            float mx = -3.4e38f;
            #pragma unroll
            for (int i = 0; i < 16; i++) mx = fmaxf(mx, sc[qi][i]);
            #pragma unroll
            for (int o = 16; o; o >>= 1) mx = fmaxf(mx, __shfl_xor_sync(0xffffffffu, mx, o));
            float sum = 0.f;
            #pragma unroll
            for (int i = 0; i < 16; i++) { sc[qi][i] = __expf(sc[qi][i] - mx); sum += sc[qi][i]; }
            #pragma unroll
            for (int o = 16; o; o >>= 1) sum += __shfl_xor_sync(0xffffffffu, sum, o);
            float inv = 1.0f / sum;
            #pragma unroll
            for (int i = 0; i < 16; i++) sc[qi][i] *= inv;
        }
        u64 av[4][8];
        #pragma unroll
        for (int qi = 0; qi < 4; qi++)
            #pragma unroll
            for (int j2 = 0; j2 < 8; j2++) av[qi][j2] = 0;
        #pragma unroll
        for (int i = 0; i < 16; i++) {
            int t = i*32 + lane;
            const float* vr = Vs + t*KVSTRIDE;
            u64 p0 = pack2(sc[0][i], sc[0][i]);
            u64 p1 = pack2(sc[1][i], sc[1][i]);
            u64 p2 = pack2(sc[2][i], sc[2][i]);
            u64 p3 = pack2(sc[3][i], sc[3][i]);
            #pragma unroll
            for (int j2 = 0; j2 < 8; j2++) {
                u64 v2 = *(const u64*)(vr + 2*j2);
                av[0][j2] = fma2(p0, v2, av[0][j2]);
                av[1][j2] = fma2(p1, v2, av[1][j2]);
                av[2][j2] = fma2(p2, v2, av[2][j2]);
                av[3][j2] = fma2(p3, v2, av[3][j2]);
            }
        }
        #pragma unroll
        for (int qi = 0; qi < 4; qi++)
            #pragma unroll
            for (int j2 = 0; j2 < 8; j2++) {
                u64 v = av[qi][j2];
                #pragma unroll
                for (int o = 16; o; o >>= 1) {
                    u64 w = __shfl_xor_sync(0xffffffffu, v, o);
                    float2 x = unpack2(v), y = unpack2(w);
                    v = pack2(x.x + y.x, x.y + y.y);
                }
                av[qi][j2] = v;
            }
        #pragma unroll
        for (int qi = 0; qi < 4; qi++)
            #pragma unroll
            for (int j2 = 0; j2 < 8; j2++)
                if (lane == qi*8 + j2)
                    *(float2*)(out + (size_t)(b*SS + s0 + qi)*DD + h*DKK + 2*j2) = unpack2(av[qi][j2]);
    }
}

// ---------------- host launcher --------------------------------------------
extern "C" void kernel_launch(void* const* d_in, const int* in_sizes, int n_in,
                              void* d_out, int out_size) {
    const float* x        = (const float*)d_in[0];
    const int*   mask     = (const int*)  d_in[1];
    const float* ln_scale = (const float*)d_in[2];
    const float* ln_bias  = (const float*)d_in[3];
    const float* dw_w     = (const float*)d_in[4];
    const float* dw_b     = (const float*)d_in[5];
    const float* pw_w     = (const float*)d_in[6];
    const float* pw_b     = (const float*)d_in[7];
    const float* Wq       = (const float*)d_in[8];
    const float* Wk       = (const float*)d_in[9];
    const float* Wv       = (const float*)d_in[10];
    const float* Wo       = (const float*)d_in[11];
    const float* att_bias = (const float*)d_in[12];
    const float* f1_w     = (const float*)d_in[13];
    const float* f1_b     = (const float*)d_in[14];
    const float* f2_w     = (const float*)d_in[15];
    const float* f2_b     = (const float*)d_in[16];
    float* out = (float*)d_out;

    float *px1, *pqkv, *patt;
    u32 *pwt;
    cudaGetSymbolAddress((void**)&px1,  g_x1);
    cudaGetSymbolAddress((void**)&pqkv, g_qkv);
    cudaGetSymbolAddress((void**)&patt, g_att);
    cudaGetSymbolAddress((void**)&pwt,  g_wt);

    const int CONV_SMEM = (70*LNS)*4 + (64*H2S*2 + 128*H2S*2)*4;       // 141408
    const int GEMM_SMEM = (64*H2S*2 + 128*H2S*2)*4;                    // 104448
    const int FFN_SMEM  = (64*H2S*2 + 128*H2S*2*2)*4;                  // 174080
    const int ASMEM     = (2*512*KVSTRIDE + 512)*4;                    // 75776
    cudaFuncSetAttribute(conv_fused_k, cudaFuncAttributeMaxDynamicSharedMemorySize, CONV_SMEM);
    cudaFuncSetAttribute(qkv_fused_k,  cudaFuncAttributeMaxDynamicSharedMemorySize, GEMM_SMEM);
    cudaFuncSetAttribute(wo_gemm_k,    cudaFuncAttributeMaxDynamicSharedMemorySize, GEMM_SMEM);
    cudaFuncSetAttribute(ffn_fused_k,  cudaFuncAttributeMaxDynamicSharedMemorySize, FFN_SMEM);
    cudaFuncSetAttribute(attention_k,  cudaFuncAttributeMaxDynamicSharedMemorySize, ASMEM);

    prep_weights_k<<<320, 256>>>(pw_w, Wq, Wk, Wv, Wo, f1_w, f2_w);
    pos_add_k<<<(MROWS*DD + 255)/256, 256>>>(x, out);   // T0 = d_out

    // conv stack, ping-pong: T0->T1->T0->T1->T0
    float* bufs[2] = { out, px1 };
    for (int i = 0; i < NCONV; i++) {
        const u32* whi = pwt + PW_OFF + (size_t)i*16384;
        conv_fused_k<<<128, 256, CONV_SMEM>>>(
            bufs[i & 1], bufs[(i & 1) ^ 1], whi, whi + 8192,
            ln_scale + i*DD, ln_bias + i*DD,
            dw_w + (size_t)i*DD*KSZ, dw_b + i*DD, pw_b + i*DD);
    }
    // after 4 layers result is back in T0 (= out)

    // attention
    qkv_fused_k<<<dim3(128,3), 256, GEMM_SMEM>>>(
        out, ln_scale + NCONV*DD, ln_bias + NCONV*DD, att_bias, pqkv);
    attention_k<<<dim3(BB*HH, 4), 256, ASMEM>>>(pqkv, mask, patt);
    wo_gemm_k<<<128, 256, GEMM_SMEM>>>(patt, att_bias, out, px1);   // T1 = attn out

    // feed-forward: reads T1, writes d_out
    ffn_fused_k<<<128, 256, FFN_SMEM>>>(
        px1, ln_scale + (NCONV+1)*DD, ln_bias + (NCONV+1)*DD, f1_b, f2_b, out);
}

// round 6
// speedup vs baseline: 3.2795x; 1.6560x over previous
#include <cuda_runtime.h>
#include <cuda_bf16.h>
#include <math.h>
#include <string.h>

// Problem constants
#define BB 16
#define SS 512
#define DD 128
#define HH 8
#define DKK 16
#define NCONV 4
#define KSZ 7
#define MROWS (BB*SS)          // 8192
#define LN_EPS 1e-5f

typedef unsigned long long u64;
typedef unsigned int u32;

// ---------------- scratch (device globals) ---------------------------------
__device__ float g_x1 [MROWS*DD];     // ping-pong partner of d_out
__device__ float g_qkv[MROWS*384];    // packed q|k|v per row
__device__ float g_att[MROWS*DD];     // attention output (pre-Wo)
__device__ u32   g_wt [163840];

#define PW_OFF   0
#define QKV_OFF  65536
#define WO_OFF   114688
#define F1_OFF   131072
#define F2_OFF   147456

// ---------------- helpers ---------------------------------------------------
__device__ __forceinline__ u32 h2u(__nv_bfloat162 h) {
    u32 u; memcpy(&u, &h, 4); return u;
}
__device__ __forceinline__ void split2(float x, float y, u32& hi, u32& lo) {
    __nv_bfloat16 hx = __float2bfloat16(x);
    __nv_bfloat16 hy = __float2bfloat16(y);
    float rx = x - __bfloat162float(hx);
    float ry = y - __bfloat162float(hy);
    __nv_bfloat162 h; h.x = hx; h.y = hy;
    __nv_bfloat162 l; l.x = __float2bfloat16(rx); l.y = __float2bfloat16(ry);
    hi = h2u(h); lo = h2u(l);
}

// ---------------- weight prep (verbatim, verified) -------------------------
__device__ __forceinline__ float wsrc(int idx,
        const float* pw_w, const float* Wq, const float* Wk, const float* Wv,
        const float* Wo, const float* f1_w, const float* f2_w) {
    if (idx < QKV_OFF) return pw_w[idx];
    if (idx < WO_OFF) {
        int r = idx - QKV_OFF;
        int n = r >> 7, k = r & 127;
        int w = n >> 7, h = (n >> 4) & 7, kk = n & 15;
        const float* W = (w == 0) ? Wq : (w == 1) ? Wk : Wv;
        return W[(h*DD + k)*DKK + kk];
    }
    if (idx < F1_OFF) {
        int r = idx - WO_OFF;
        int n = r >> 7, k = r & 127;
        return Wo[k*DD + n];
    }
    if (idx < F2_OFF) return f1_w[idx - F1_OFF];
    return f2_w[idx - F2_OFF];
}

__global__ void prep_weights_k(const float* __restrict__ pw_w,
                               const float* __restrict__ Wq,
                               const float* __restrict__ Wk,
                               const float* __restrict__ Wv,
                               const float* __restrict__ Wo,
                               const float* __restrict__ f1_w,
                               const float* __restrict__ f2_w) {
    int p = blockIdx.x * blockDim.x + threadIdx.x;
    if (p >= 81920) return;
    int e = p * 2;
    float v0 = wsrc(e,   pw_w, Wq, Wk, Wv, Wo, f1_w, f2_w);
    float v1 = wsrc(e+1, pw_w, Wq, Wk, Wv, Wo, f1_w, f2_w);
    u32 hi, lo;
    split2(v0, v1, hi, lo);
    int base, losz, r;
    if (e < QKV_OFF)      { int unit = e >> 14; base = unit*16384; r = e & 16383; losz = 8192; }
    else if (e < WO_OFF)  { base = QKV_OFF; r = e - QKV_OFF; losz = 24576; }
    else if (e < F1_OFF)  { base = WO_OFF;  r = e - WO_OFF;  losz = 8192; }
    else if (e < F2_OFF)  { base = F1_OFF;  r = e - F1_OFF;  losz = 8192; }
    else                  { base = F2_OFF;  r = e - F2_OFF;  losz = 8192; }
    int n = r >> 7, kp = (r >> 1) & 63;
    g_wt[base + n*64 + kp]        = hi;
    g_wt[base + losz + n*64 + kp] = lo;
}

// ---------------- positional signal add ------------------------------------
__global__ void pos_add_k(const float* __restrict__ x, float* __restrict__ out) {
    int idx = blockIdx.x * blockDim.x + threadIdx.x;
    if (idx >= MROWS*DD) return;
    int d = idx & (DD-1);
    int s = (idx >> 7) & (SS-1);
    const float inc = 9.210340371976184f / 63.0f;
    float v;
    if (d < 64) v = sinf((float)s * expf(-(float)d * inc));
    else        v = cosf((float)s * expf(-(float)(d-64) * inc));
    out[idx] = x[idx] + v;
}

// ================= shared GEMM machinery (256 threads, 8 warps) ============
#define H2S 68
#define MMA_BF16(acc, a, b) \
    asm volatile("mma.sync.aligned.m16n8k16.row.col.f32.bf16.bf16.f32 " \
        "{%0,%1,%2,%3}, {%4,%5,%6,%7}, {%8,%9}, {%0,%1,%2,%3};\n" \
        : "+f"(acc[0]), "+f"(acc[1]), "+f"(acc[2]), "+f"(acc[3]) \
        : "r"(a[0]), "r"(a[1]), "r"(a[2]), "r"(a[3]), "r"(b[0]), "r"(b[1]))

__device__ __forceinline__ void load_B(u32* Bh, u32* Bl,
        const u32* __restrict__ Whi, const u32* __restrict__ Wlo, int tid) {
    #pragma unroll
    for (int i = 0; i < 8; i++) {
        int idx = i*256 + tid;
        int r = idx >> 4, c4 = (idx & 15) << 2;
        *(uint4*)(Bh + r*H2S + c4) = *(const uint4*)(Whi + (size_t)r*64 + c4);
        *(uint4*)(Bl + r*H2S + c4) = *(const uint4*)(Wlo + (size_t)r*64 + c4);
    }
}

__device__ __forceinline__ void mma_main(float acc[2][4][4],
        const u32* Ah, const u32* Al, const u32* Bh, const u32* Bl,
        int warpM, int warpN, int g, int tg) {
    #pragma unroll
    for (int kt = 0; kt < 8; kt++) {
        int kb = kt * 8;
        u32 ah[2][4], al[2][4], bh[4][2], bl[4][2];
        #pragma unroll
        for (int mi = 0; mi < 2; mi++) {
            const u32* p = Ah + (warpM*32 + mi*16 + g)*H2S + kb + tg;
            ah[mi][0] = p[0]; ah[mi][1] = p[8*H2S]; ah[mi][2] = p[4]; ah[mi][3] = p[8*H2S + 4];
            const u32* q = Al + (warpM*32 + mi*16 + g)*H2S + kb + tg;
            al[mi][0] = q[0]; al[mi][1] = q[8*H2S]; al[mi][2] = q[4]; al[mi][3] = q[8*H2S + 4];
        }
        #pragma unroll
        for (int ni = 0; ni < 4; ni++) {
            const u32* p = Bh + (warpN*32 + ni*8 + g)*H2S + kb + tg;
            bh[ni][0] = p[0]; bh[ni][1] = p[4];
            const u32* q = Bl + (warpN*32 + ni*8 + g)*H2S + kb + tg;
            bl[ni][0] = q[0]; bl[ni][1] = q[4];
        }
        #pragma unroll
        for (int mi = 0; mi < 2; mi++)
            #pragma unroll
            for (int ni = 0; ni < 4; ni++) {
                MMA_BF16(acc[mi][ni], ah[mi], bh[ni]);
                MMA_BF16(acc[mi][ni], al[mi], bh[ni]);
                MMA_BF16(acc[mi][ni], ah[mi], bl[ni]);
            }
    }
}

__device__ __forceinline__ void ln_to_A(u32* Ah, u32* Al,
        const float* __restrict__ X, int m0,
        const float* __restrict__ gamma, const float* __restrict__ beta,
        int warp, int lane) {
    float4 g4 = ((const float4*)gamma)[lane];
    float4 b4 = ((const float4*)beta)[lane];
    #pragma unroll
    for (int i = 0; i < 8; i++) {
        int r = warp*8 + i;
        float4 v = ((const float4*)(X + (size_t)(m0+r)*DD))[lane];
        float sum = v.x + v.y + v.z + v.w;
        #pragma unroll
        for (int o = 16; o; o >>= 1) sum += __shfl_xor_sync(0xffffffffu, sum, o);
        float mu = sum * (1.0f/128.0f);
        float dx = v.x-mu, dy = v.y-mu, dz = v.z-mu, dw = v.w-mu;
        float sq = dx*dx + dy*dy + dz*dz + dw*dw;
        #pragma unroll
        for (int o = 16; o; o >>= 1) sq += __shfl_xor_sync(0xffffffffu, sq, o);
        float rstd = rsqrtf(sq * (1.0f/128.0f) + LN_EPS);
        float nx = dx*rstd*g4.x + b4.x;
        float ny = dy*rstd*g4.y + b4.y;
        float nz = dz*rstd*g4.z + b4.z;
        float nw = dw*rstd*g4.w + b4.w;
        u32 h0, l0, h1, l1;
        split2(nx, ny, h0, l0);
        split2(nz, nw, h1, l1);
        int o2 = r*H2S + lane*2;
        Ah[o2] = h0; Ah[o2+1] = h1;
        Al[o2] = l0; Al[o2+1] = l1;
    }
}

// ---------------- fused conv layer (verbatim from R5, verified) ------------
#define LNS 132
__global__ __launch_bounds__(256) void conv_fused_k(
        const float* __restrict__ In, float* __restrict__ Out,
        const u32* __restrict__ Whi, const u32* __restrict__ Wlo,
        const float* __restrict__ gamma, const float* __restrict__ beta,
        const float* __restrict__ dw_w, const float* __restrict__ dw_b,
        const float* __restrict__ pw_b) {
    extern __shared__ u32 smg[];
    float* LNb = (float*)smg;
    u32* Ah = smg + 70*LNS;
    u32* Al = Ah + 64*H2S;
    u32* Bh = Al + 64*H2S;
    u32* Bl = Bh + 128*H2S;

    int tid = threadIdx.x;
    int warp = tid >> 5, lane = tid & 31;
    int m0 = blockIdx.x * 64;
    int b = m0 >> 9, s0 = m0 & (SS-1);

    load_B(Bh, Bl, Whi, Wlo, tid);

    float4 g4 = ((const float4*)gamma)[lane];
    float4 be4 = ((const float4*)beta)[lane];
    #pragma unroll
    for (int it = 0; it < 9; it++) {
        int li = warp + it*8;
        if (li >= 70) break;
        int st = s0 - 3 + li;
        if ((unsigned)st < SS) {
            float4 v = ((const float4*)(In + (size_t)(b*SS+st)*DD))[lane];
            float sum = v.x + v.y + v.z + v.w;
            #pragma unroll
            for (int o = 16; o; o >>= 1) sum += __shfl_xor_sync(0xffffffffu, sum, o);
            float mu = sum * (1.0f/128.0f);
            float dx = v.x-mu, dy = v.y-mu, dz = v.z-mu, dw = v.w-mu;
            float sq = dx*dx + dy*dy + dz*dz + dw*dw;
            #pragma unroll
            for (int o = 16; o; o >>= 1) sq += __shfl_xor_sync(0xffffffffu, sq, o);
            float rstd = rsqrtf(sq * (1.0f/128.0f) + LN_EPS);
            float4 r;
            r.x = dx*rstd*g4.x + be4.x;
            r.y = dy*rstd*g4.y + be4.y;
            r.z = dz*rstd*g4.z + be4.z;
            r.w = dw*rstd*g4.w + be4.w;
            *(float4*)(LNb + li*LNS + lane*4) = r;
        }
    }
    __syncthreads();

    {
        int p = tid & 63, rq = tid >> 6;
        int c = 2*p;
        float w0[KSZ], w1[KSZ];
        #pragma unroll
        for (int j = 0; j < KSZ; j++) {
            w0[j] = dw_w[c*KSZ + j];
            w1[j] = dw_w[(c+1)*KSZ + j];
        }
        float bb0 = dw_b[c], bb1 = dw_b[c+1];
        #pragma unroll
        for (int i = 0; i < 16; i++) {
            int r = i*4 + rq;
            float a0 = bb0, a1 = bb1;
            #pragma unroll
            for (int j = 0; j < KSZ; j++) {
                int st = s0 + r - 3 + j;
                if ((unsigned)st < SS) {
                    float2 hv = *(const float2*)(LNb + (r+j)*LNS + c);
                    a0 += hv.x * w0[j];
                    a1 += hv.y * w1[j];
                }
            }
            u32 hi, lo;
            split2(a0, a1, hi, lo);
            Ah[r*H2S + p] = hi;
            Al[r*H2S + p] = lo;
        }
    }
    __syncthreads();

    int warpM = warp >> 2, warpN = warp & 3;
    int g = lane >> 2, tg = lane & 3;
    float acc[2][4][4];
    #pragma unroll
    for (int mi = 0; mi < 2; mi++)
        #pragma unroll
        for (int ni = 0; ni < 4; ni++)
            #pragma unroll
            for (int c = 0; c < 4; c++) acc[mi][ni][c] = 0.0f;

    mma_main(acc, Ah, Al, Bh, Bl, warpM, warpN, g, tg);

    #pragma unroll
    for (int ni = 0; ni < 4; ni++) {
        int col = warpN*32 + ni*8 + 2*tg;
        float2 bv = *(const float2*)(pw_b + col);
        #pragma unroll
        for (int mi = 0; mi < 2; mi++) {
            int r0 = m0 + warpM*32 + mi*16 + g;
            float2 v0 = make_float2(fmaxf(acc[mi][ni][0] + bv.x, 0.f),
                                    fmaxf(acc[mi][ni][1] + bv.y, 0.f));
            float2 v1 = make_float2(fmaxf(acc[mi][ni][2] + bv.x, 0.f),
                                    fmaxf(acc[mi][ni][3] + bv.y, 0.f));
            float2 r0v = *(const float2*)(In + (size_t)r0*DD + col);
            float2 r1v = *(const float2*)(In + (size_t)(r0+8)*DD + col);
            v0.x += r0v.x; v0.y += r0v.y;
            v1.x += r1v.x; v1.y += r1v.y;
            *(float2*)(Out + (size_t)r0*DD + col) = v0;
            *(float2*)(Out + (size_t)(r0+8)*DD + col) = v1;
        }
    }
}

// ---------------- fused LN + QKV GEMM (verbatim) ---------------------------
__global__ __launch_bounds__(256) void qkv_fused_k(
        const float* __restrict__ In,
        const float* __restrict__ gamma, const float* __restrict__ beta,
        const float* __restrict__ att_bias, float* __restrict__ Outqkv) {
    extern __shared__ u32 smg[];
    u32* Ah = smg;
    u32* Al = Ah + 64*H2S;
    u32* Bh = Al + 64*H2S;
    u32* Bl = Bh + 128*H2S;
    int tid = threadIdx.x;
    int warp = tid >> 5, lane = tid & 31;
    int m0 = blockIdx.x * 64;
    int n0 = blockIdx.y * 128;

    load_B(Bh, Bl, g_wt + QKV_OFF + (size_t)(blockIdx.y)*128*64,
                   g_wt + QKV_OFF + 24576 + (size_t)(blockIdx.y)*128*64, tid);
    ln_to_A(Ah, Al, In, m0, gamma, beta, warp, lane);
    __syncthreads();

    int warpM = warp >> 2, warpN = warp & 3;
    int g = lane >> 2, tg = lane & 3;
    float acc[2][4][4];
    #pragma unroll
    for (int mi = 0; mi < 2; mi++)
        #pragma unroll
        for (int ni = 0; ni < 4; ni++)
            #pragma unroll
            for (int c = 0; c < 4; c++) acc[mi][ni][c] = 0.0f;

    mma_main(acc, Ah, Al, Bh, Bl, warpM, warpN, g, tg);

    float b0 = att_bias[0];
    #pragma unroll
    for (int ni = 0; ni < 4; ni++) {
        int col = n0 + warpN*32 + ni*8 + 2*tg;
        #pragma unroll
        for (int mi = 0; mi < 2; mi++) {
            int r0 = m0 + warpM*32 + mi*16 + g;
            float2 v0 = make_float2(acc[mi][ni][0] + b0, acc[mi][ni][1] + b0);
            float2 v1 = make_float2(acc[mi][ni][2] + b0, acc[mi][ni][3] + b0);
            *(float2*)(Outqkv + (size_t)r0*384 + col) = v0;
            *(float2*)(Outqkv + (size_t)(r0+8)*384 + col) = v1;
        }
    }
}

// ---------------- Wo GEMM (verbatim) ---------------------------------------
__global__ __launch_bounds__(256) void wo_gemm_k(
        const float* __restrict__ A, const float* __restrict__ att_bias,
        const float* __restrict__ res, float* __restrict__ Out) {
    extern __shared__ u32 smg[];
    u32* Ah = smg;
    u32* Al = Ah + 64*H2S;
    u32* Bh = Al + 64*H2S;
    u32* Bl = Bh + 128*H2S;
    int tid = threadIdx.x;
    int warp = tid >> 5, lane = tid & 31;
    int m0 = blockIdx.x * 64;

    load_B(Bh, Bl, g_wt + WO_OFF, g_wt + WO_OFF + 8192, tid);
    #pragma unroll
    for (int i = 0; i < 8; i++) {
        int r = warp*8 + i;
        float4 v = ((const float4*)(A + (size_t)(m0+r)*DD))[lane];
        u32 h0, l0, h1, l1;
        split2(v.x, v.y, h0, l0);
        split2(v.z, v.w, h1, l1);
        int o2 = r*H2S + lane*2;
        Ah[o2] = h0; Ah[o2+1] = h1;
        Al[o2] = l0; Al[o2+1] = l1;
    }
    __syncthreads();

    int warpM = warp >> 2, warpN = warp & 3;
    int g = lane >> 2, tg = lane & 3;
    float acc[2][4][4];
    #pragma unroll
    for (int mi = 0; mi < 2; mi++)
        #pragma unroll
        for (int ni = 0; ni < 4; ni++)
            #pragma unroll
            for (int c = 0; c < 4; c++) acc[mi][ni][c] = 0.0f;

    mma_main(acc, Ah, Al, Bh, Bl, warpM, warpN, g, tg);

    float b0 = att_bias[0];
    #pragma unroll
    for (int ni = 0; ni < 4; ni++) {
        int col = warpN*32 + ni*8 + 2*tg;
        #pragma unroll
        for (int mi = 0; mi < 2; mi++) {
            int r0 = m0 + warpM*32 + mi*16 + g;
            float2 r0v = *(const float2*)(res + (size_t)r0*DD + col);
            float2 r1v = *(const float2*)(res + (size_t)(r0+8)*DD + col);
            float2 v0 = make_float2(acc[mi][ni][0] + b0 + r0v.x, acc[mi][ni][1] + b0 + r0v.y);
            float2 v1 = make_float2(acc[mi][ni][2] + b0 + r1v.x, acc[mi][ni][3] + b0 + r1v.y);
            *(float2*)(Out + (size_t)r0*DD + col) = v0;
            *(float2*)(Out + (size_t)(r0+8)*DD + col) = v1;
        }
    }
}

// ---------------- fused FFN (verbatim) -------------------------------------
__global__ __launch_bounds__(256) void ffn_fused_k(
        const float* __restrict__ In,
        const float* __restrict__ gamma, const float* __restrict__ beta,
        const float* __restrict__ f1_b, const float* __restrict__ f2_b,
        float* __restrict__ Out) {
    extern __shared__ u32 smg[];
    u32* Ah  = smg;
    u32* Al  = Ah + 64*H2S;
    u32* Bh1 = Al + 64*H2S;
    u32* Bl1 = Bh1 + 128*H2S;
    u32* Bh2 = Bl1 + 128*H2S;
    u32* Bl2 = Bh2 + 128*H2S;
    int tid = threadIdx.x;
    int warp = tid >> 5, lane = tid & 31;
    int m0 = blockIdx.x * 64;

    load_B(Bh1, Bl1, g_wt + F1_OFF, g_wt + F1_OFF + 8192, tid);
    load_B(Bh2, Bl2, g_wt + F2_OFF, g_wt + F2_OFF + 8192, tid);
    ln_to_A(Ah, Al, In, m0, gamma, beta, warp, lane);
    __syncthreads();

    int warpM = warp >> 2, warpN = warp & 3;
    int g = lane >> 2, tg = lane & 3;
    float acc[2][4][4];
    #pragma unroll
    for (int mi = 0; mi < 2; mi++)
        #pragma unroll
        for (int ni = 0; ni < 4; ni++)
            #pragma unroll
            for (int c = 0; c < 4; c++) acc[mi][ni][c] = 0.0f;

    mma_main(acc, Ah, Al, Bh1, Bl1, warpM, warpN, g, tg);
    __syncthreads();

    #pragma unroll
    for (int ni = 0; ni < 4; ni++) {
        int col = warpN*32 + ni*8 + 2*tg;
        float2 bv = *(const float2*)(f1_b + col);
        #pragma unroll
        for (int mi = 0; mi < 2; mi++) {
            int r = warpM*32 + mi*16 + g;
            float x0 = fmaxf(acc[mi][ni][0] + bv.x, 0.f);
            float y0 = fmaxf(acc[mi][ni][1] + bv.y, 0.f);
            float x1 = fmaxf(acc[mi][ni][2] + bv.x, 0.f);
            float y1 = fmaxf(acc[mi][ni][3] + bv.y, 0.f);
            u32 hi, lo;
            split2(x0, y0, hi, lo);
            Ah[r*H2S + (col>>1)] = hi; Al[r*H2S + (col>>1)] = lo;
            split2(x1, y1, hi, lo);
            Ah[(r+8)*H2S + (col>>1)] = hi; Al[(r+8)*H2S + (col>>1)] = lo;
        }
    }
    __syncthreads();

    #pragma unroll
    for (int mi = 0; mi < 2; mi++)
        #pragma unroll
        for (int ni = 0; ni < 4; ni++)
            #pragma unroll
            for (int c = 0; c < 4; c++) acc[mi][ni][c] = 0.0f;

    mma_main(acc, Ah, Al, Bh2, Bl2, warpM, warpN, g, tg);

    #pragma unroll
    for (int ni = 0; ni < 4; ni++) {
        int col = warpN*32 + ni*8 + 2*tg;
        float2 bv = *(const float2*)(f2_b + col);
        #pragma unroll
        for (int mi = 0; mi < 2; mi++) {
            int r0 = m0 + warpM*32 + mi*16 + g;
            float2 r0v = *(const float2*)(In + (size_t)r0*DD + col);
            float2 r1v = *(const float2*)(In + (size_t)(r0+8)*DD + col);
            float2 v0 = make_float2(acc[mi][ni][0] + bv.x + r0v.x, acc[mi][ni][1] + bv.y + r0v.y);
            float2 v1 = make_float2(acc[mi][ni][2] + bv.x + r1v.x, acc[mi][ni][3] + bv.y + r1v.y);
            *(float2*)(Out + (size_t)r0*DD + col) = v0;
            *(float2*)(Out + (size_t)(r0+8)*DD + col) = v1;
        }
    }
}

// ---------------- NEW: flash-style MMA attention ---------------------------
// grid (B*H, 4 qtiles of 128); 256 threads = 8 warps; warp owns 16 q rows.
// K/V in smem as bf16 hi/lo; Q/K scores and P*V via 3-term bf16x3 MMA.
#define KSTR 12      // u32 stride per K row (8 used + 4 pad; conflict-free)
#define VSTR 260     // u32 stride per Vt row (256 used + 4 pad)
__global__ __launch_bounds__(256) void attention_mma_k(
        const float* __restrict__ qkv, const int* __restrict__ mask,
        float* __restrict__ out) {
    extern __shared__ u32 smg[];
    u32* Khi  = smg;                    // [512][12]
    u32* Klo  = Khi + 512*KSTR;
    u32* Vthi = Klo + 512*KSTR;         // [16][260]  (transposed V)
    u32* Vtlo = Vthi + 16*VSTR;
    float* mb = (float*)(Vtlo + 16*VSTR);  // [512]

    int bh = blockIdx.x;
    int b = bh >> 3, h = bh & 7;
    int tid = threadIdx.x;
    int warp = tid >> 5, lane = tid & 31;
    int g = lane >> 2, tg = lane & 3;

    // ---- stage K (rows) as packed bf16 hi/lo ----
    for (int idx = tid; idx < 512*4; idx += 256) {
        int t = idx >> 2, j = idx & 3;          // j-th float4 of K row
        float4 kv = *(const float4*)(qkv + (size_t)(b*SS + t)*384 + 128 + h*DKK + j*4);
        u32 h0, l0, h1, l1;
        split2(kv.x, kv.y, h0, l0);
        split2(kv.z, kv.w, h1, l1);
        Khi[t*KSTR + 2*j]     = h0;  Khi[t*KSTR + 2*j + 1] = h1;
        Klo[t*KSTR + 2*j]     = l0;  Klo[t*KSTR + 2*j + 1] = l1;
    }
    // ---- stage V transposed: Vt[d][keypair] ----
    for (int idx = tid; idx < 16*256; idx += 256) {
        int d = idx >> 8, kp = idx & 255;
        float v0 = qkv[(size_t)(b*SS + 2*kp    )*384 + 256 + h*DKK + d];
        float v1 = qkv[(size_t)(b*SS + 2*kp + 1)*384 + 256 + h*DKK + d];
        u32 hi, lo;
        split2(v0, v1, hi, lo);
        Vthi[d*VSTR + kp] = hi;
        Vtlo[d*VSTR + kp] = lo;
    }
    for (int t = tid; t < SS; t += 256)
        mb[t] = mask[b*SS + t] ? 0.0f : -1e30f;
    __syncthreads();

    // ---- Q fragments (rows warp*16 + {g, g+8}) ----
    int qrow = b*SS + blockIdx.y*128 + warp*16;
    u32 qh[4], ql[4];
    {
        const float* qp0 = qkv + (size_t)(qrow + g    )*384 + h*DKK;
        const float* qp1 = qkv + (size_t)(qrow + 8 + g)*384 + h*DKK;
        float2 A0 = *(const float2*)(qp0 + 2*tg);
        float2 A1 = *(const float2*)(qp1 + 2*tg);
        float2 A2 = *(const float2*)(qp0 + 2*tg + 8);
        float2 A3 = *(const float2*)(qp1 + 2*tg + 8);
        split2(A0.x, A0.y, qh[0], ql[0]);
        split2(A1.x, A1.y, qh[1], ql[1]);
        split2(A2.x, A2.y, qh[2], ql[2]);
        split2(A3.x, A3.y, qh[3], ql[3]);
    }

    // ---- online softmax state (rows g, g+8) + output accumulators ----
    float m0 = -1e30f, m1 = -1e30f, l0 = 0.f, l1 = 0.f;
    float o[2][4];
    #pragma unroll
    for (int vd = 0; vd < 2; vd++)
        #pragma unroll
        for (int c = 0; c < 4; c++) o[vd][c] = 0.f;

    #pragma unroll
    for (int c = 0; c < 4; c++) {          // key chunks of 128
        int k0 = c * 128;
        float s[16][4];
        #pragma unroll
        for (int nt = 0; nt < 16; nt++) {
            s[nt][0] = s[nt][1] = s[nt][2] = s[nt][3] = 0.f;
            int t = k0 + nt*8 + g;
            u32 kh[2], kl[2];
            kh[0] = Khi[t*KSTR + tg];  kh[1] = Khi[t*KSTR + tg + 4];
            kl[0] = Klo[t*KSTR + tg];  kl[1] = Klo[t*KSTR + tg + 4];
            MMA_BF16(s[nt], qh, kh);
            MMA_BF16(s[nt], ql, kh);
            MMA_BF16(s[nt], qh, kl);
        }
        // scale + mask + chunk max
        float cm0 = -1e30f, cm1 = -1e30f;
        #pragma unroll
        for (int nt = 0; nt < 16; nt++) {
            float2 mv = *(const float2*)(mb + k0 + nt*8 + 2*tg);
            s[nt][0] = s[nt][0]*0.25f + mv.x;
            s[nt][1] = s[nt][1]*0.25f + mv.y;
            s[nt][2] = s[nt][2]*0.25f + mv.x;
            s[nt][3] = s[nt][3]*0.25f + mv.y;
            cm0 = fmaxf(cm0, fmaxf(s[nt][0], s[nt][1]));
            cm1 = fmaxf(cm1, fmaxf(s[nt][2], s[nt][3]));
        }
        cm0 = fmaxf(cm0, __shfl_xor_sync(0xffffffffu, cm0, 1));
        cm0 = fmaxf(cm0, __shfl_xor_sync(0xffffffffu, cm0, 2));
        cm1 = fmaxf(cm1, __shfl_xor_sync(0xffffffffu, cm1, 1));
        cm1 = fmaxf(cm1, __shfl_xor_sync(0xffffffffu, cm1, 2));
        float nm0 = fmaxf(m0, cm0), nm1 = fmaxf(m1, cm1);
        float al0 = __expf(m0 - nm0), al1 = __expf(m1 - nm1);
        m0 = nm0; m1 = nm1;
        #pragma unroll
        for (int vd = 0; vd < 2; vd++) {
            o[vd][0] *= al0; o[vd][1] *= al0;
            o[vd][2] *= al1; o[vd][3] *= al1;
        }
        // exp + row sums
        float ls0 = 0.f, ls1 = 0.f;
        #pragma unroll
        for (int nt = 0; nt < 16; nt++) {
            s[nt][0] = __expf(s[nt][0] - nm0);
            s[nt][1] = __expf(s[nt][1] - nm0);
            s[nt][2] = __expf(s[nt][2] - nm1);
            s[nt][3] = __expf(s[nt][3] - nm1);
            ls0 += s[nt][0] + s[nt][1];
            ls1 += s[nt][2] + s[nt][3];
        }
        ls0 += __shfl_xor_sync(0xffffffffu, ls0, 1);
        ls0 += __shfl_xor_sync(0xffffffffu, ls0, 2);
        ls1 += __shfl_xor_sync(0xffffffffu, ls1, 1);
        ls1 += __shfl_xor_sync(0xffffffffu, ls1, 2);
        l0 = al0*l0 + ls0;
        l1 = al1*l1 + ls1;
        // P * V  (P straight from accumulators, repacked as A-fragments)
        #pragma unroll
        for (int kc = 0; kc < 8; kc++) {
            u32 ph[4], pl[4];
            split2(s[2*kc][0],   s[2*kc][1],   ph[0], pl[0]);
            split2(s[2*kc][2],   s[2*kc][3],   ph[1], pl[1]);
            split2(s[2*kc+1][0], s[2*kc+1][1], ph[2], pl[2]);
            split2(s[2*kc+1][2], s[2*kc+1][3], ph[3], pl[3]);
            #pragma unroll
            for (int vd = 0; vd < 2; vd++) {
                int vr = (vd*8 + g)*VSTR + c*64 + kc*8 + tg;
                u32 vh[2], vl[2];
                vh[0] = Vthi[vr];  vh[1] = Vthi[vr + 4];
                vl[0] = Vtlo[vr];  vl[1] = Vtlo[vr + 4];
                MMA_BF16(o[vd], ph, vh);
                MMA_BF16(o[vd], pl, vh);
                MMA_BF16(o[vd], ph, vl);
            }
        }
    }

    // ---- normalize + write ----
    float inv0 = 1.0f / l0, inv1 = 1.0f / l1;
    #pragma unroll
    for (int vd = 0; vd < 2; vd++) {
        int col = h*DKK + vd*8 + 2*tg;
        *(float2*)(out + (size_t)(qrow + g    )*DD + col) =
            make_float2(o[vd][0]*inv0, o[vd][1]*inv0);
        *(float2*)(out + (size_t)(qrow + 8 + g)*DD + col) =
            make_float2(o[vd][2]*inv1, o[vd][3]*inv1);
    }
}

// ---------------- host launcher --------------------------------------------
extern "C" void kernel_launch(void* const* d_in, const int* in_sizes, int n_in,
                              void* d_out, int out_size) {
    const float* x        = (const float*)d_in[0];
    const int*   mask     = (const int*)  d_in[1];
    const float* ln_scale = (const float*)d_in[2];
    const float* ln_bias  = (const float*)d_in[3];
    const float* dw_w     = (const float*)d_in[4];
    const float* dw_b     = (const float*)d_in[5];
    const float* pw_w     = (const float*)d_in[6];
    const float* pw_b     = (const float*)d_in[7];
    const float* Wq       = (const float*)d_in[8];
    const float* Wk       = (const float*)d_in[9];
    const float* Wv       = (const float*)d_in[10];
    const float* Wo       = (const float*)d_in[11];
    const float* att_bias = (const float*)d_in[12];
    const float* f1_w     = (const float*)d_in[13];
    const float* f1_b     = (const float*)d_in[14];
    const float* f2_w     = (const float*)d_in[15];
    const float* f2_b     = (const float*)d_in[16];
    float* out = (float*)d_out;

    float *px1, *pqkv, *patt;
    u32 *pwt;
    cudaGetSymbolAddress((void**)&px1,  g_x1);
    cudaGetSymbolAddress((void**)&pqkv, g_qkv);
    cudaGetSymbolAddress((void**)&patt, g_att);
    cudaGetSymbolAddress((void**)&pwt,  g_wt);

    const int CONV_SMEM = (70*LNS)*4 + (64*H2S*2 + 128*H2S*2)*4;
    const int GEMM_SMEM = (64*H2S*2 + 128*H2S*2)*4;
    const int FFN_SMEM  = (64*H2S*2 + 128*H2S*2*2)*4;
    const int ASMEM     = (2*512*KSTR + 2*16*VSTR + 512)*4;   // 84480
    cudaFuncSetAttribute(conv_fused_k,    cudaFuncAttributeMaxDynamicSharedMemorySize, CONV_SMEM);
    cudaFuncSetAttribute(qkv_fused_k,     cudaFuncAttributeMaxDynamicSharedMemorySize, GEMM_SMEM);
    cudaFuncSetAttribute(wo_gemm_k,       cudaFuncAttributeMaxDynamicSharedMemorySize, GEMM_SMEM);
    cudaFuncSetAttribute(ffn_fused_k,     cudaFuncAttributeMaxDynamicSharedMemorySize, FFN_SMEM);
    cudaFuncSetAttribute(attention_mma_k, cudaFuncAttributeMaxDynamicSharedMemorySize, ASMEM);

    prep_weights_k<<<320, 256>>>(pw_w, Wq, Wk, Wv, Wo, f1_w, f2_w);
    pos_add_k<<<(MROWS*DD + 255)/256, 256>>>(x, out);

    float* bufs[2] = { out, px1 };
    for (int i = 0; i < NCONV; i++) {
        const u32* whi = pwt + PW_OFF + (size_t)i*16384;
        conv_fused_k<<<128, 256, CONV_SMEM>>>(
            bufs[i & 1], bufs[(i & 1) ^ 1], whi, whi + 8192,
            ln_scale + i*DD, ln_bias + i*DD,
            dw_w + (size_t)i*DD*KSZ, dw_b + i*DD, pw_b + i*DD);
    }

    qkv_fused_k<<<dim3(128,3), 256, GEMM_SMEM>>>(
        out, ln_scale + NCONV*DD, ln_bias + NCONV*DD, att_bias, pqkv);
    attention_mma_k<<<dim3(BB*HH, 4), 256, ASMEM>>>(pqkv, mask, patt);
    wo_gemm_k<<<128, 256, GEMM_SMEM>>>(patt, att_bias, out, px1);

    ffn_fused_k<<<128, 256, FFN_SMEM>>>(
        px1, ln_scale + (NCONV+1)*DD, ln_bias + (NCONV+1)*DD, f1_b, f2_b, out);
}

// round 8
// speedup vs baseline: 3.4269x; 1.0450x over previous
#include <cuda_runtime.h>
#include <cuda_bf16.h>
#include <math.h>
#include <string.h>

#define BB 16
#define SS 512
#define DD 128
#define HH 8
#define DKK 16
#define NCONV 4
#define KSZ 7
#define MROWS (BB*SS)
#define LN_EPS 1e-5f

typedef unsigned long long u64;
typedef unsigned int u32;

__device__ float g_x1 [MROWS*DD];
__device__ float g_qkv[MROWS*384];
__device__ float g_att[MROWS*DD];
__device__ u32   g_wt [163840];

#define PW_OFF   0
#define QKV_OFF  65536
#define WO_OFF   114688
#define F1_OFF   131072
#define F2_OFF   147456

__device__ __forceinline__ u32 h2u(__nv_bfloat162 h) {
    u32 u; memcpy(&u, &h, 4); return u;
}
__device__ __forceinline__ void split2(float x, float y, u32& hi, u32& lo) {
    __nv_bfloat16 hx = __float2bfloat16(x);
    __nv_bfloat16 hy = __float2bfloat16(y);
    float rx = x - __bfloat162float(hx);
    float ry = y - __bfloat162float(hy);
    __nv_bfloat162 h; h.x = hx; h.y = hy;
    __nv_bfloat162 l; l.x = __float2bfloat16(rx); l.y = __float2bfloat16(ry);
    hi = h2u(h); lo = h2u(l);
}

// ---------------- weight prep (verbatim, verified) -------------------------
__device__ __forceinline__ float wsrc(int idx,
        const float* pw_w, const float* Wq, const float* Wk, const float* Wv,
        const float* Wo, const float* f1_w, const float* f2_w) {
    if (idx < QKV_OFF) return pw_w[idx];
    if (idx < WO_OFF) {
        int r = idx - QKV_OFF;
        int n = r >> 7, k = r & 127;
        int w = n >> 7, h = (n >> 4) & 7, kk = n & 15;
        const float* W = (w == 0) ? Wq : (w == 1) ? Wk : Wv;
        return W[(h*DD + k)*DKK + kk];
    }
    if (idx < F1_OFF) {
        int r = idx - WO_OFF;
        int n = r >> 7, k = r & 127;
        return Wo[k*DD + n];
    }
    if (idx < F2_OFF) return f1_w[idx - F1_OFF];
    return f2_w[idx - F2_OFF];
}

__global__ void prep_weights_k(const float* __restrict__ pw_w,
                               const float* __restrict__ Wq,
                               const float* __restrict__ Wk,
                               const float* __restrict__ Wv,
                               const float* __restrict__ Wo,
                               const float* __restrict__ f1_w,
                               const float* __restrict__ f2_w) {
    int p = blockIdx.x * blockDim.x + threadIdx.x;
    if (p >= 81920) return;
    int e = p * 2;
    float v0 = wsrc(e,   pw_w, Wq, Wk, Wv, Wo, f1_w, f2_w);
    float v1 = wsrc(e+1, pw_w, Wq, Wk, Wv, Wo, f1_w, f2_w);
    u32 hi, lo;
    split2(v0, v1, hi, lo);
    int base, losz, r;
    if (e < QKV_OFF)      { int unit = e >> 14; base = unit*16384; r = e & 16383; losz = 8192; }
    else if (e < WO_OFF)  { base = QKV_OFF; r = e - QKV_OFF; losz = 24576; }
    else if (e < F1_OFF)  { base = WO_OFF;  r = e - WO_OFF;  losz = 8192; }
    else if (e < F2_OFF)  { base = F1_OFF;  r = e - F1_OFF;  losz = 8192; }
    else                  { base = F2_OFF;  r = e - F2_OFF;  losz = 8192; }
    int n = r >> 7, kp = (r >> 1) & 63;
    g_wt[base + n*64 + kp]        = hi;
    g_wt[base + losz + n*64 + kp] = lo;
}

// ---------------- positional signal add ------------------------------------
__global__ void pos_add_k(const float* __restrict__ x, float* __restrict__ out) {
    int idx = blockIdx.x * blockDim.x + threadIdx.x;
    if (idx >= MROWS*DD) return;
    int d = idx & (DD-1);
    int s = (idx >> 7) & (SS-1);
    const float inc = 9.210340371976184f / 63.0f;
    float v;
    if (d < 64) v = sinf((float)s * expf(-(float)d * inc));
    else        v = cosf((float)s * expf(-(float)(d-64) * inc));
    out[idx] = x[idx] + v;
}

// ================= GEMM machinery ==========================================
#define H2S 68
#define MMA_BF16(acc, a, b) \
    asm volatile("mma.sync.aligned.m16n8k16.row.col.f32.bf16.bf16.f32 " \
        "{%0,%1,%2,%3}, {%4,%5,%6,%7}, {%8,%9}, {%0,%1,%2,%3};\n" \
        : "+f"(acc[0]), "+f"(acc[1]), "+f"(acc[2]), "+f"(acc[3]) \
        : "r"(a[0]), "r"(a[1]), "r"(a[2]), "r"(a[3]), "r"(b[0]), "r"(b[1]))

__device__ __forceinline__ void load_B(u32* Bh, u32* Bl,
        const u32* __restrict__ Whi, const u32* __restrict__ Wlo, int tid) {
    #pragma unroll
    for (int i = 0; i < 8; i++) {
        int idx = i*256 + tid;
        int r = idx >> 4, c4 = (idx & 15) << 2;
        *(uint4*)(Bh + r*H2S + c4) = *(const uint4*)(Whi + (size_t)r*64 + c4);
        *(uint4*)(Bl + r*H2S + c4) = *(const uint4*)(Wlo + (size_t)r*64 + c4);
    }
}

// 32-row M-tile main loop: warpM in {0,1} covers rows warpM*16 + 0..15
__device__ __forceinline__ void mma_main32(float acc[4][4],
        const u32* Ah, const u32* Al, const u32* Bh, const u32* Bl,
        int warpM, int warpN, int g, int tg) {
    #pragma unroll
    for (int kt = 0; kt < 8; kt++) {
        int kb = kt * 8;
        u32 ah[4], al[4], bh[4][2], bl[4][2];
        const u32* p = Ah + (warpM*16 + g)*H2S + kb + tg;
        ah[0] = p[0]; ah[1] = p[8*H2S]; ah[2] = p[4]; ah[3] = p[8*H2S + 4];
        const u32* q = Al + (warpM*16 + g)*H2S + kb + tg;
        al[0] = q[0]; al[1] = q[8*H2S]; al[2] = q[4]; al[3] = q[8*H2S + 4];
        #pragma unroll
        for (int ni = 0; ni < 4; ni++) {
            const u32* pb = Bh + (warpN*32 + ni*8 + g)*H2S + kb + tg;
            bh[ni][0] = pb[0]; bh[ni][1] = pb[4];
            const u32* qb = Bl + (warpN*32 + ni*8 + g)*H2S + kb + tg;
            bl[ni][0] = qb[0]; bl[ni][1] = qb[4];
        }
        #pragma unroll
        for (int ni = 0; ni < 4; ni++) {
            MMA_BF16(acc[ni], ah, bh[ni]);
            MMA_BF16(acc[ni], al, bh[ni]);
            MMA_BF16(acc[ni], ah, bl[ni]);
        }
    }
}

// 64-row version (used by FFN, verbatim semantics from R6)
__device__ __forceinline__ void mma_main(float acc[2][4][4],
        const u32* Ah, const u32* Al, const u32* Bh, const u32* Bl,
        int warpM, int warpN, int g, int tg) {
    #pragma unroll
    for (int kt = 0; kt < 8; kt++) {
        int kb = kt * 8;
        u32 ah[2][4], al[2][4], bh[4][2], bl[4][2];
        #pragma unroll
        for (int mi = 0; mi < 2; mi++) {
            const u32* p = Ah + (warpM*32 + mi*16 + g)*H2S + kb + tg;
            ah[mi][0] = p[0]; ah[mi][1] = p[8*H2S]; ah[mi][2] = p[4]; ah[mi][3] = p[8*H2S + 4];
            const u32* q = Al + (warpM*32 + mi*16 + g)*H2S + kb + tg;
            al[mi][0] = q[0]; al[mi][1] = q[8*H2S]; al[mi][2] = q[4]; al[mi][3] = q[8*H2S + 4];
        }
        #pragma unroll
        for (int ni = 0; ni < 4; ni++) {
            const u32* p = Bh + (warpN*32 + ni*8 + g)*H2S + kb + tg;
            bh[ni][0] = p[0]; bh[ni][1] = p[4];
            const u32* q = Bl + (warpN*32 + ni*8 + g)*H2S + kb + tg;
            bl[ni][0] = q[0]; bl[ni][1] = q[4];
        }
        #pragma unroll
        for (int mi = 0; mi < 2; mi++)
            #pragma unroll
            for (int ni = 0; ni < 4; ni++) {
                MMA_BF16(acc[mi][ni], ah[mi], bh[ni]);
                MMA_BF16(acc[mi][ni], al[mi], bh[ni]);
                MMA_BF16(acc[mi][ni], ah[mi], bl[ni]);
            }
    }
}

// LN 32 tile rows -> Ah/Al (4 rows per warp)
__device__ __forceinline__ void ln_to_A32(u32* Ah, u32* Al,
        const float* __restrict__ X, int m0,
        const float* __restrict__ gamma, const float* __restrict__ beta,
        int warp, int lane) {
    float4 g4 = ((const float4*)gamma)[lane];
    float4 b4 = ((const float4*)beta)[lane];
    #pragma unroll
    for (int i = 0; i < 4; i++) {
        int r = warp*4 + i;
        float4 v = ((const float4*)(X + (size_t)(m0+r)*DD))[lane];
        float sum = v.x + v.y + v.z + v.w;
        #pragma unroll
        for (int o = 16; o; o >>= 1) sum += __shfl_xor_sync(0xffffffffu, sum, o);
        float mu = sum * (1.0f/128.0f);
        float dx = v.x-mu, dy = v.y-mu, dz = v.z-mu, dw = v.w-mu;
        float sq = dx*dx + dy*dy + dz*dz + dw*dw;
        #pragma unroll
        for (int o = 16; o; o >>= 1) sq += __shfl_xor_sync(0xffffffffu, sq, o);
        float rstd = rsqrtf(sq * (1.0f/128.0f) + LN_EPS);
        float nx = dx*rstd*g4.x + b4.x;
        float ny = dy*rstd*g4.y + b4.y;
        float nz = dz*rstd*g4.z + b4.z;
        float nw = dw*rstd*g4.w + b4.w;
        u32 h0, l0, h1, l1;
        split2(nx, ny, h0, l0);
        split2(nz, nw, h1, l1);
        int o2 = r*H2S + lane*2;
        Ah[o2] = h0; Ah[o2+1] = h1;
        Al[o2] = l0; Al[o2+1] = l1;
    }
}

// LN 64 tile rows (FFN)
__device__ __forceinline__ void ln_to_A(u32* Ah, u32* Al,
        const float* __restrict__ X, int m0,
        const float* __restrict__ gamma, const float* __restrict__ beta,
        int warp, int lane) {
    float4 g4 = ((const float4*)gamma)[lane];
    float4 b4 = ((const float4*)beta)[lane];
    #pragma unroll
    for (int i = 0; i < 8; i++) {
        int r = warp*8 + i;
        float4 v = ((const float4*)(X + (size_t)(m0+r)*DD))[lane];
        float sum = v.x + v.y + v.z + v.w;
        #pragma unroll
        for (int o = 16; o; o >>= 1) sum += __shfl_xor_sync(0xffffffffu, sum, o);
        float mu = sum * (1.0f/128.0f);
        float dx = v.x-mu, dy = v.y-mu, dz = v.z-mu, dw = v.w-mu;
        float sq = dx*dx + dy*dy + dz*dz + dw*dw;
        #pragma unroll
        for (int o = 16; o; o >>= 1) sq += __shfl_xor_sync(0xffffffffu, sq, o);
        float rstd = rsqrtf(sq * (1.0f/128.0f) + LN_EPS);
        float nx = dx*rstd*g4.x + b4.x;
        float ny = dy*rstd*g4.y + b4.y;
        float nz = dz*rstd*g4.z + b4.z;
        float nw = dw*rstd*g4.w + b4.w;
        u32 h0, l0, h1, l1;
        split2(nx, ny, h0, l0);
        split2(nz, nw, h1, l1);
        int o2 = r*H2S + lane*2;
        Ah[o2] = h0; Ah[o2+1] = h1;
        Al[o2] = l0; Al[o2+1] = l1;
    }
}

// ---------------- fused conv layer: 32-row tile, grid 256 ------------------
#define LNS 132
__global__ __launch_bounds__(256) void conv_fused_k(
        const float* __restrict__ In, float* __restrict__ Out,
        const u32* __restrict__ Whi, const u32* __restrict__ Wlo,
        const float* __restrict__ gamma, const float* __restrict__ beta,
        const float* __restrict__ dw_w, const float* __restrict__ dw_b,
        const float* __restrict__ pw_b) {
    extern __shared__ u32 smg[];
    float* LNb = (float*)smg;            // [38][132]
    u32* Ah = smg + 38*LNS;              // [32][68]
    u32* Al = Ah + 32*H2S;
    u32* Bh = Al + 32*H2S;               // [128][68]
    u32* Bl = Bh + 128*H2S;

    int tid = threadIdx.x;
    int warp = tid >> 5, lane = tid & 31;
    int m0 = blockIdx.x * 32;
    int b = m0 >> 9, s0 = m0 & (SS-1);

    load_B(Bh, Bl, Whi, Wlo, tid);

    float4 g4 = ((const float4*)gamma)[lane];
    float4 be4 = ((const float4*)beta)[lane];
    #pragma unroll
    for (int it = 0; it < 5; it++) {
        int li = warp + it*8;
        if (li >= 38) break;
        int st = s0 - 3 + li;
        if ((unsigned)st < SS) {
            float4 v = ((const float4*)(In + (size_t)(b*SS+st)*DD))[lane];
            float sum = v.x + v.y + v.z + v.w;
            #pragma unroll
            for (int o = 16; o; o >>= 1) sum += __shfl_xor_sync(0xffffffffu, sum, o);
            float mu = sum * (1.0f/128.0f);
            float dx = v.x-mu, dy = v.y-mu, dz = v.z-mu, dw = v.w-mu;
            float sq = dx*dx + dy*dy + dz*dz + dw*dw;
            #pragma unroll
            for (int o = 16; o; o >>= 1) sq += __shfl_xor_sync(0xffffffffu, sq, o);
            float rstd = rsqrtf(sq * (1.0f/128.0f) + LN_EPS);
            float4 r;
            r.x = dx*rstd*g4.x + be4.x;
            r.y = dy*rstd*g4.y + be4.y;
            r.z = dz*rstd*g4.z + be4.z;
            r.w = dw*rstd*g4.w + be4.w;
            *(float4*)(LNb + li*LNS + lane*4) = r;
        }
    }
    __syncthreads();

    {   // depthwise: thread owns col pair c for 8 rows
        int p = tid & 63, rq = tid >> 6;
        int c = 2*p;
        float w0[KSZ], w1[KSZ];
        #pragma unroll
        for (int j = 0; j < KSZ; j++) {
            w0[j] = dw_w[c*KSZ + j];
            w1[j] = dw_w[(c+1)*KSZ + j];
        }
        float bb0 = dw_b[c], bb1 = dw_b[c+1];
        #pragma unroll
        for (int i = 0; i < 8; i++) {
            int r = i*4 + rq;
            float a0 = bb0, a1 = bb1;
            #pragma unroll
            for (int j = 0; j < KSZ; j++) {
                int st = s0 + r - 3 + j;
                if ((unsigned)st < SS) {
                    float2 hv = *(const float2*)(LNb + (r+j)*LNS + c);
                    a0 += hv.x * w0[j];
                    a1 += hv.y * w1[j];
                }
            }
            u32 hi, lo;
            split2(a0, a1, hi, lo);
            Ah[r*H2S + p] = hi;
            Al[r*H2S + p] = lo;
        }
    }
    __syncthreads();

    int warpM = warp >> 2, warpN = warp & 3;
    int g = lane >> 2, tg = lane & 3;
    float acc[4][4];
    #pragma unroll
    for (int ni = 0; ni < 4; ni++)
        #pragma unroll
        for (int c = 0; c < 4; c++) acc[ni][c] = 0.0f;

    mma_main32(acc, Ah, Al, Bh, Bl, warpM, warpN, g, tg);

    #pragma unroll
    for (int ni = 0; ni < 4; ni++) {
        int col = warpN*32 + ni*8 + 2*tg;
        float2 bv = *(const float2*)(pw_b + col);
        int r0 = m0 + warpM*16 + g;
        float2 v0 = make_float2(fmaxf(acc[ni][0] + bv.x, 0.f),
                                fmaxf(acc[ni][1] + bv.y, 0.f));
        float2 v1 = make_float2(fmaxf(acc[ni][2] + bv.x, 0.f),
                                fmaxf(acc[ni][3] + bv.y, 0.f));
        float2 r0v = *(const float2*)(In + (size_t)r0*DD + col);
        float2 r1v = *(const float2*)(In + (size_t)(r0+8)*DD + col);
        v0.x += r0v.x; v0.y += r0v.y;
        v1.x += r1v.x; v1.y += r1v.y;
        *(float2*)(Out + (size_t)r0*DD + col) = v0;
        *(float2*)(Out + (size_t)(r0+8)*DD + col) = v1;
    }
}

// ---------------- fused LN + QKV GEMM: 32-row tile, grid (256,3) -----------
__global__ __launch_bounds__(256) void qkv_fused_k(
        const float* __restrict__ In,
        const float* __restrict__ gamma, const float* __restrict__ beta,
        const float* __restrict__ att_bias, float* __restrict__ Outqkv) {
    extern __shared__ u32 smg[];
    u32* Ah = smg;                       // [32][68]
    u32* Al = Ah + 32*H2S;
    u32* Bh = Al + 32*H2S;
    u32* Bl = Bh + 128*H2S;
    int tid = threadIdx.x;
    int warp = tid >> 5, lane = tid & 31;
    int m0 = blockIdx.x * 32;
    int n0 = blockIdx.y * 128;

    load_B(Bh, Bl, g_wt + QKV_OFF + (size_t)(blockIdx.y)*128*64,
                   g_wt + QKV_OFF + 24576 + (size_t)(blockIdx.y)*128*64, tid);
    ln_to_A32(Ah, Al, In, m0, gamma, beta, warp, lane);
    __syncthreads();

    int warpM = warp >> 2, warpN = warp & 3;
    int g = lane >> 2, tg = lane & 3;
    float acc[4][4];
    #pragma unroll
    for (int ni = 0; ni < 4; ni++)
        #pragma unroll
        for (int c = 0; c < 4; c++) acc[ni][c] = 0.0f;

    mma_main32(acc, Ah, Al, Bh, Bl, warpM, warpN, g, tg);

    float b0 = att_bias[0];
    #pragma unroll
    for (int ni = 0; ni < 4; ni++) {
        int col = n0 + warpN*32 + ni*8 + 2*tg;
        int r0 = m0 + warpM*16 + g;
        float2 v0 = make_float2(acc[ni][0] + b0, acc[ni][1] + b0);
        float2 v1 = make_float2(acc[ni][2] + b0, acc[ni][3] + b0);
        *(float2*)(Outqkv + (size_t)r0*384 + col) = v0;
        *(float2*)(Outqkv + (size_t)(r0+8)*384 + col) = v1;
    }
}

// ---------------- Wo GEMM: 32-row tile, grid 256 ---------------------------
__global__ __launch_bounds__(256) void wo_gemm_k(
        const float* __restrict__ A, const float* __restrict__ att_bias,
        const float* __restrict__ res, float* __restrict__ Out) {
    extern __shared__ u32 smg[];
    u32* Ah = smg;
    u32* Al = Ah + 32*H2S;
    u32* Bh = Al + 32*H2S;
    u32* Bl = Bh + 128*H2S;
    int tid = threadIdx.x;
    int warp = tid >> 5, lane = tid & 31;
    int m0 = blockIdx.x * 32;

    load_B(Bh, Bl, g_wt + WO_OFF, g_wt + WO_OFF + 8192, tid);
    #pragma unroll
    for (int i = 0; i < 4; i++) {
        int r = warp*4 + i;
        float4 v = ((const float4*)(A + (size_t)(m0+r)*DD))[lane];
        u32 h0, l0, h1, l1;
        split2(v.x, v.y, h0, l0);
        split2(v.z, v.w, h1, l1);
        int o2 = r*H2S + lane*2;
        Ah[o2] = h0; Ah[o2+1] = h1;
        Al[o2] = l0; Al[o2+1] = l1;
    }
    __syncthreads();

    int warpM = warp >> 2, warpN = warp & 3;
    int g = lane >> 2, tg = lane & 3;
    float acc[4][4];
    #pragma unroll
    for (int ni = 0; ni < 4; ni++)
        #pragma unroll
        for (int c = 0; c < 4; c++) acc[ni][c] = 0.0f;

    mma_main32(acc, Ah, Al, Bh, Bl, warpM, warpN, g, tg);

    float b0 = att_bias[0];
    #pragma unroll
    for (int ni = 0; ni < 4; ni++) {
        int col = warpN*32 + ni*8 + 2*tg;
        int r0 = m0 + warpM*16 + g;
        float2 r0v = *(const float2*)(res + (size_t)r0*DD + col);
        float2 r1v = *(const float2*)(res + (size_t)(r0+8)*DD + col);
        float2 v0 = make_float2(acc[ni][0] + b0 + r0v.x, acc[ni][1] + b0 + r0v.y);
        float2 v1 = make_float2(acc[ni][2] + b0 + r1v.x, acc[ni][3] + b0 + r1v.y);
        *(float2*)(Out + (size_t)r0*DD + col) = v0;
        *(float2*)(Out + (size_t)(r0+8)*DD + col) = v1;
    }
}

// ---------------- fused FFN (verbatim from R6) -----------------------------
__global__ __launch_bounds__(256) void ffn_fused_k(
        const float* __restrict__ In,
        const float* __restrict__ gamma, const float* __restrict__ beta,
        const float* __restrict__ f1_b, const float* __restrict__ f2_b,
        float* __restrict__ Out) {
    extern __shared__ u32 smg[];
    u32* Ah  = smg;
    u32* Al  = Ah + 64*H2S;
    u32* Bh1 = Al + 64*H2S;
    u32* Bl1 = Bh1 + 128*H2S;
    u32* Bh2 = Bl1 + 128*H2S;
    u32* Bl2 = Bh2 + 128*H2S;
    int tid = threadIdx.x;
    int warp = tid >> 5, lane = tid & 31;
    int m0 = blockIdx.x * 64;

    load_B(Bh1, Bl1, g_wt + F1_OFF, g_wt + F1_OFF + 8192, tid);
    load_B(Bh2, Bl2, g_wt + F2_OFF, g_wt + F2_OFF + 8192, tid);
    ln_to_A(Ah, Al, In, m0, gamma, beta, warp, lane);
    __syncthreads();

    int warpM = warp >> 2, warpN = warp & 3;
    int g = lane >> 2, tg = lane & 3;
    float acc[2][4][4];
    #pragma unroll
    for (int mi = 0; mi < 2; mi++)
        #pragma unroll
        for (int ni = 0; ni < 4; ni++)
            #pragma unroll
            for (int c = 0; c < 4; c++) acc[mi][ni][c] = 0.0f;

    mma_main(acc, Ah, Al, Bh1, Bl1, warpM, warpN, g, tg);
    __syncthreads();

    #pragma unroll
    for (int ni = 0; ni < 4; ni++) {
        int col = warpN*32 + ni*8 + 2*tg;
        float2 bv = *(const float2*)(f1_b + col);
        #pragma unroll
        for (int mi = 0; mi < 2; mi++) {
            int r = warpM*32 + mi*16 + g;
            float x0 = fmaxf(acc[mi][ni][0] + bv.x, 0.f);
            float y0 = fmaxf(acc[mi][ni][1] + bv.y, 0.f);
            float x1 = fmaxf(acc[mi][ni][2] + bv.x, 0.f);
            float y1 = fmaxf(acc[mi][ni][3] + bv.y, 0.f);
            u32 hi, lo;
            split2(x0, y0, hi, lo);
            Ah[r*H2S + (col>>1)] = hi; Al[r*H2S + (col>>1)] = lo;
            split2(x1, y1, hi, lo);
            Ah[(r+8)*H2S + (col>>1)] = hi; Al[(r+8)*H2S + (col>>1)] = lo;
        }
    }
    __syncthreads();

    #pragma unroll
    for (int mi = 0; mi < 2; mi++)
        #pragma unroll
        for (int ni = 0; ni < 4; ni++)
            #pragma unroll
            for (int c = 0; c < 4; c++) acc[mi][ni][c] = 0.0f;

    mma_main(acc, Ah, Al, Bh2, Bl2, warpM, warpN, g, tg);

    #pragma unroll
    for (int ni = 0; ni < 4; ni++) {
        int col = warpN*32 + ni*8 + 2*tg;
        float2 bv = *(const float2*)(f2_b + col);
        #pragma unroll
        for (int mi = 0; mi < 2; mi++) {
            int r0 = m0 + warpM*32 + mi*16 + g;
            float2 r0v = *(const float2*)(In + (size_t)r0*DD + col);
            float2 r1v = *(const float2*)(In + (size_t)(r0+8)*DD + col);
            float2 v0 = make_float2(acc[mi][ni][0] + bv.x + r0v.x, acc[mi][ni][1] + bv.y + r0v.y);
            float2 v1 = make_float2(acc[mi][ni][2] + bv.x + r1v.x, acc[mi][ni][3] + bv.y + r1v.y);
            *(float2*)(Out + (size_t)r0*DD + col) = v0;
            *(float2*)(Out + (size_t)(r0+8)*DD + col) = v1;
        }
    }
}

// ---------------- flash MMA attention (staging improved) -------------------
#define KSTR 12
#define VSTR 260
#define VSTG 20     // fp32 staging stride (16B aligned rows)
__global__ __launch_bounds__(256) void attention_mma_k(
        const float* __restrict__ qkv, const int* __restrict__ mask,
        float* __restrict__ out) {
    extern __shared__ u32 smg[];
    u32* Khi  = smg;                        // [512][12]
    u32* Klo  = Khi + 512*KSTR;
    u32* Vthi = Klo + 512*KSTR;             // [16][260]
    u32* Vtlo = Vthi + 16*VSTR;
    float* mb = (float*)(Vtlo + 16*VSTR);   // [512]
    float* Vstage = mb + 512;               // [256][20] fp32

    int bh = blockIdx.x;
    int b = bh >> 3, h = bh & 7;
    int tid = threadIdx.x;
    int warp = tid >> 5, lane = tid & 31;
    int g = lane >> 2, tg = lane & 3;

    // ---- stage K rows as packed bf16 hi/lo ----
    for (int idx = tid; idx < 512*4; idx += 256) {
        int t = idx >> 2, j = idx & 3;
        float4 kv = *(const float4*)(qkv + (size_t)(b*SS + t)*384 + 128 + h*DKK + j*4);
        u32 h0, l0, h1, l1;
        split2(kv.x, kv.y, h0, l0);
        split2(kv.z, kv.w, h1, l1);
        Khi[t*KSTR + 2*j]     = h0;  Khi[t*KSTR + 2*j + 1] = h1;
        Klo[t*KSTR + 2*j]     = l0;  Klo[t*KSTR + 2*j + 1] = l1;
    }
    for (int t = tid; t < SS; t += 256)
        mb[t] = mask[b*SS + t] ? 0.0f : -1e30f;

    // ---- stage V transposed in 2 halves via coalesced fp32 staging ----
    #pragma unroll
    for (int half = 0; half < 2; half++) {
        __syncthreads();
        for (int idx = tid; idx < 256*4; idx += 256) {
            int key = idx >> 2, d4 = (idx & 3) * 4;
            float4 v = *(const float4*)(qkv + (size_t)(b*SS + half*256 + key)*384 + 256 + h*DKK + d4);
            *(float4*)(Vstage + key*VSTG + d4) = v;
        }
        __syncthreads();
        for (int idx = tid; idx < 16*128; idx += 256) {
            int kp = idx >> 4, d = idx & 15;
            float v0 = Vstage[(2*kp)*VSTG + d];
            float v1 = Vstage[(2*kp+1)*VSTG + d];
            u32 hi, lo;
            split2(v0, v1, hi, lo);
            Vthi[d*VSTR + half*128 + kp] = hi;
            Vtlo[d*VSTR + half*128 + kp] = lo;
        }
    }
    __syncthreads();

    // ---- Q fragments ----
    int qrow = b*SS + blockIdx.y*128 + warp*16;
    u32 qh[4], ql[4];
    {
        const float* qp0 = qkv + (size_t)(qrow + g    )*384 + h*DKK;
        const float* qp1 = qkv + (size_t)(qrow + 8 + g)*384 + h*DKK;
        float2 A0 = *(const float2*)(qp0 + 2*tg);
        float2 A1 = *(const float2*)(qp1 + 2*tg);
        float2 A2 = *(const float2*)(qp0 + 2*tg + 8);
        float2 A3 = *(const float2*)(qp1 + 2*tg + 8);
        split2(A0.x, A0.y, qh[0], ql[0]);
        split2(A1.x, A1.y, qh[1], ql[1]);
        split2(A2.x, A2.y, qh[2], ql[2]);
        split2(A3.x, A3.y, qh[3], ql[3]);
    }

    float m0 = -1e30f, m1 = -1e30f, l0 = 0.f, l1 = 0.f;
    float o[2][4];
    #pragma unroll
    for (int vd = 0; vd < 2; vd++)
        #pragma unroll
        for (int c = 0; c < 4; c++) o[vd][c] = 0.f;

    #pragma unroll
    for (int c = 0; c < 4; c++) {
        int k0 = c * 128;
        float s[16][4];
        #pragma unroll
        for (int nt = 0; nt < 16; nt++) {
            s[nt][0] = s[nt][1] = s[nt][2] = s[nt][3] = 0.f;
            int t = k0 + nt*8 + g;
            u32 kh[2], kl[2];
            kh[0] = Khi[t*KSTR + tg];  kh[1] = Khi[t*KSTR + tg + 4];
            kl[0] = Klo[t*KSTR + tg];  kl[1] = Klo[t*KSTR + tg + 4];
            MMA_BF16(s[nt], qh, kh);
            MMA_BF16(s[nt], ql, kh);
            MMA_BF16(s[nt], qh, kl);
        }
        float cm0 = -1e30f, cm1 = -1e30f;
        #pragma unroll
        for (int nt = 0; nt < 16; nt++) {
            float2 mv = *(const float2*)(mb + k0 + nt*8 + 2*tg);
            s[nt][0] = s[nt][0]*0.25f + mv.x;
            s[nt][1] = s[nt][1]*0.25f + mv.y;
            s[nt][2] = s[nt][2]*0.25f + mv.x;
            s[nt][3] = s[nt][3]*0.25f + mv.y;
            cm0 = fmaxf(cm0, fmaxf(s[nt][0], s[nt][1]));
            cm1 = fmaxf(cm1, fmaxf(s[nt][2], s[nt][3]));
        }
        cm0 = fmaxf(cm0, __shfl_xor_sync(0xffffffffu, cm0, 1));
        cm0 = fmaxf(cm0, __shfl_xor_sync(0xffffffffu, cm0, 2));
        cm1 = fmaxf(cm1, __shfl_xor_sync(0xffffffffu, cm1, 1));
        cm1 = fmaxf(cm1, __shfl_xor_sync(0xffffffffu, cm1, 2));
        float nm0 = fmaxf(m0, cm0), nm1 = fmaxf(m1, cm1);
        float al0 = __expf(m0 - nm0), al1 = __expf(m1 - nm1);
        m0 = nm0; m1 = nm1;
        #pragma unroll
        for (int vd = 0; vd < 2; vd++) {
            o[vd][0] *= al0; o[vd][1] *= al0;
            o[vd][2] *= al1; o[vd][3] *= al1;
        }
        float ls0 = 0.f, ls1 = 0.f;
        #pragma unroll
        for (int nt = 0; nt < 16; nt++) {
            s[nt][0] = __expf(s[nt][0] - nm0);
            s[nt][1] = __expf(s[nt][1] - nm0);
            s[nt][2] = __expf(s[nt][2] - nm1);
            s[nt][3] = __expf(s[nt][3] - nm1);
            ls0 += s[nt][0] + s[nt][1];
            ls1 += s[nt][2] + s[nt][3];
        }
        ls0 += __shfl_xor_sync(0xffffffffu, ls0, 1);
        ls0 += __shfl_xor_sync(0xffffffffu, ls0, 2);
        ls1 += __shfl_xor_sync(0xffffffffu, ls1, 1);
        ls1 += __shfl_xor_sync(0xffffffffu, ls1, 2);
        l0 = al0*l0 + ls0;
        l1 = al1*l1 + ls1;
        #pragma unroll
        for (int kc = 0; kc < 8; kc++) {
            u32 ph[4], pl[4];
            split2(s[2*kc][0],   s[2*kc][1],   ph[0], pl[0]);
            split2(s[2*kc][2],   s[2*kc][3],   ph[1], pl[1]);
            split2(s[2*kc+1][0], s[2*kc+1][1], ph[2], pl[2]);
            split2(s[2*kc+1][2], s[2*kc+1][3], ph[3], pl[3]);
            #pragma unroll
            for (int vd = 0; vd < 2; vd++) {
                int vr = (vd*8 + g)*VSTR + c*64 + kc*8 + tg;
                u32 vh[2], vl[2];
                vh[0] = Vthi[vr];  vh[1] = Vthi[vr + 4];
                vl[0] = Vtlo[vr];  vl[1] = Vtlo[vr + 4];
                MMA_BF16(o[vd], ph, vh);
                MMA_BF16(o[vd], pl, vh);
                MMA_BF16(o[vd], ph, vl);
            }
        }
    }

    float inv0 = 1.0f / l0, inv1 = 1.0f / l1;
    #pragma unroll
    for (int vd = 0; vd < 2; vd++) {
        int col = h*DKK + vd*8 + 2*tg;
        *(float2*)(out + (size_t)(qrow + g    )*DD + col) =
            make_float2(o[vd][0]*inv0, o[vd][1]*inv0);
        *(float2*)(out + (size_t)(qrow + 8 + g)*DD + col) =
            make_float2(o[vd][2]*inv1, o[vd][3]*inv1);
    }
}

// ---------------- host launcher --------------------------------------------
extern "C" void kernel_launch(void* const* d_in, const int* in_sizes, int n_in,
                              void* d_out, int out_size) {
    const float* x        = (const float*)d_in[0];
    const int*   mask     = (const int*)  d_in[1];
    const float* ln_scale = (const float*)d_in[2];
    const float* ln_bias  = (const float*)d_in[3];
    const float* dw_w     = (const float*)d_in[4];
    const float* dw_b     = (const float*)d_in[5];
    const float* pw_w     = (const float*)d_in[6];
    const float* pw_b     = (const float*)d_in[7];
    const float* Wq       = (const float*)d_in[8];
    const float* Wk       = (const float*)d_in[9];
    const float* Wv       = (const float*)d_in[10];
    const float* Wo       = (const float*)d_in[11];
    const float* att_bias = (const float*)d_in[12];
    const float* f1_w     = (const float*)d_in[13];
    const float* f1_b     = (const float*)d_in[14];
    const float* f2_w     = (const float*)d_in[15];
    const float* f2_b     = (const float*)d_in[16];
    float* out = (float*)d_out;

    float *px1, *pqkv, *patt;
    u32 *pwt;
    cudaGetSymbolAddress((void**)&px1,  g_x1);
    cudaGetSymbolAddress((void**)&pqkv, g_qkv);
    cudaGetSymbolAddress((void**)&patt, g_att);
    cudaGetSymbolAddress((void**)&pwt,  g_wt);

    const int CONV_SMEM = (38*LNS)*4 + (32*H2S*2 + 128*H2S*2)*4;   // 107,168
    const int GEMM_SMEM = (32*H2S*2 + 128*H2S*2)*4;                // 87,040
    const int FFN_SMEM  = (64*H2S*2 + 128*H2S*2*2)*4;              // 174,080
    const int ASMEM     = (2*512*KSTR + 2*16*VSTR + 512 + 256*VSTG)*4;  // 104,960
    cudaFuncSetAttribute(conv_fused_k,    cudaFuncAttributeMaxDynamicSharedMemorySize, CONV_SMEM);
    cudaFuncSetAttribute(qkv_fused_k,     cudaFuncAttributeMaxDynamicSharedMemorySize, GEMM_SMEM);
    cudaFuncSetAttribute(wo_gemm_k,       cudaFuncAttributeMaxDynamicSharedMemorySize, GEMM_SMEM);
    cudaFuncSetAttribute(ffn_fused_k,     cudaFuncAttributeMaxDynamicSharedMemorySize, FFN_SMEM);
    cudaFuncSetAttribute(attention_mma_k, cudaFuncAttributeMaxDynamicSharedMemorySize, ASMEM);

    prep_weights_k<<<320, 256>>>(pw_w, Wq, Wk, Wv, Wo, f1_w, f2_w);
    pos_add_k<<<(MROWS*DD + 255)/256, 256>>>(x, out);

    float* bufs[2] = { out, px1 };
    for (int i = 0; i < NCONV; i++) {
        const u32* whi = pwt + PW_OFF + (size_t)i*16384;
        conv_fused_k<<<256, 256, CONV_SMEM>>>(
            bufs[i & 1], bufs[(i & 1) ^ 1], whi, whi + 8192,
            ln_scale + i*DD, ln_bias + i*DD,
            dw_w + (size_t)i*DD*KSZ, dw_b + i*DD, pw_b + i*DD);
    }

    qkv_fused_k<<<dim3(256,3), 256, GEMM_SMEM>>>(
        out, ln_scale + NCONV*DD, ln_bias + NCONV*DD, att_bias, pqkv);
    attention_mma_k<<<dim3(BB*HH, 4), 256, ASMEM>>>(pqkv, mask, patt);
    wo_gemm_k<<<256, 256, GEMM_SMEM>>>(patt, att_bias, out, px1);

    ffn_fused_k<<<128, 256, FFN_SMEM>>>(
        px1, ln_scale + (NCONV+1)*DD, ln_bias + (NCONV+1)*DD, f1_b, f2_b, out);
}